// round 1
// baseline (speedup 1.0000x reference)
#include <cuda_runtime.h>
#include <cuda_bf16.h>
#include <cstdint>
#include <cstdio>

// Problem constants: B=2, S=2048, D=1024, H=16, hd=64, FF=4096
#define BB 2
#define SS 2048
#define DD 1024
#define HH 16
#define HD 64
#define FF_DIM 4096
#define MTOK (BB*SS)          // 4096 rows

// ---------------------------------------------------------------------------
// Scratch (device globals; no allocation allowed)
// ---------------------------------------------------------------------------
__device__ float g_qkv[(size_t)MTOK * 3 * DD];   // [4096, 3072]
__device__ float g_attn[(size_t)MTOK * DD];      // [4096, 1024]
__device__ float g_h1pre[(size_t)MTOK * DD];
__device__ float g_h1[(size_t)MTOK * DD];
__device__ float g_mid[(size_t)MTOK * FF_DIM];   // [4096, 4096]
__device__ float g_h2pre[(size_t)MTOK * DD];

// ---------------------------------------------------------------------------
// SGEMM: C[M,N] = A[M,K] @ W[N,K]^T + bias[N]  (+res)  (+relu)
// BM=BN=128, BK=16, 256 threads, 8x8 per-thread microtile.
// Requires M%128==0, N%128==0, K%16==0 (true for all calls here).
// ---------------------------------------------------------------------------
__global__ __launch_bounds__(256) void sgemm_k(
    const float* __restrict__ A, const float* __restrict__ W,
    const float* __restrict__ bias, const float* __restrict__ res,
    float* __restrict__ C, int M, int N, int K, int relu)
{
    __shared__ float As[16][128];
    __shared__ float Ws[16][128];

    const int tid = threadIdx.x;
    const int bm = blockIdx.y * 128;
    const int bn = blockIdx.x * 128;
    const int tx = tid & 15;         // 0..15
    const int ty = tid >> 4;         // 0..15

    const int lrow = tid >> 2;       // 0..63
    const int lc4  = (tid & 3) * 4;  // 0,4,8,12

    float acc[8][8];
#pragma unroll
    for (int i = 0; i < 8; ++i)
#pragma unroll
        for (int j = 0; j < 8; ++j) acc[i][j] = 0.f;

    for (int kk = 0; kk < K; kk += 16) {
#pragma unroll
        for (int r = 0; r < 128; r += 64) {
            float4 av = *(const float4*)(A + (size_t)(bm + lrow + r) * K + kk + lc4);
            As[lc4 + 0][lrow + r] = av.x;
            As[lc4 + 1][lrow + r] = av.y;
            As[lc4 + 2][lrow + r] = av.z;
            As[lc4 + 3][lrow + r] = av.w;
            float4 wv = *(const float4*)(W + (size_t)(bn + lrow + r) * K + kk + lc4);
            Ws[lc4 + 0][lrow + r] = wv.x;
            Ws[lc4 + 1][lrow + r] = wv.y;
            Ws[lc4 + 2][lrow + r] = wv.z;
            Ws[lc4 + 3][lrow + r] = wv.w;
        }
        __syncthreads();

#pragma unroll
        for (int k = 0; k < 16; ++k) {
            float a[8], b[8];
            *(float4*)(a)     = *(const float4*)&As[k][ty * 8];
            *(float4*)(a + 4) = *(const float4*)&As[k][ty * 8 + 4];
            *(float4*)(b)     = *(const float4*)&Ws[k][tx * 8];
            *(float4*)(b + 4) = *(const float4*)&Ws[k][tx * 8 + 4];
#pragma unroll
            for (int i = 0; i < 8; ++i)
#pragma unroll
                for (int j = 0; j < 8; ++j)
                    acc[i][j] += a[i] * b[j];
        }
        __syncthreads();
    }

#pragma unroll
    for (int i = 0; i < 8; ++i) {
        const int row = bm + ty * 8 + i;
        const size_t base = (size_t)row * N + bn + tx * 8;
#pragma unroll
        for (int j = 0; j < 8; ++j) {
            float v = acc[i][j] + bias[bn + tx * 8 + j];
            if (res)  v += res[base + j];
            if (relu) v = fmaxf(v, 0.f);
            C[base + j] = v;
        }
    }
}

// ---------------------------------------------------------------------------
// Copy K / V cache slices out of the packed QKV buffer.
// qkv rows are 3072 wide: [q(1024) | k(1024) | v(1024)]
// ---------------------------------------------------------------------------
__global__ __launch_bounds__(256) void copy_kv_k(
    const float* __restrict__ qkv, float* __restrict__ kd, float* __restrict__ vd)
{
    int i = blockIdx.x * blockDim.x + threadIdx.x;    // over 4096*256 float4
    int row = i >> 8;            // 256 float4 per 1024-wide row
    int c   = i & 255;
    const float4* src = (const float4*)(qkv + (size_t)row * 3072);
    ((float4*)kd)[i] = src[256 + c];
    ((float4*)vd)[i] = src[512 + c];
}

// ---------------------------------------------------------------------------
// Flash attention, fp32, causal. One block = one (b,h,q-tile of 64).
// 256 threads: tid = qi*4 + seg; thread owns O dims [seg*16, seg*16+16) of
// query row qi and score columns kj = seg + 4*jj. P exchanged via shfl.
// ---------------------------------------------------------------------------
#define FL_PAD 68
#define FLASH_SMEM (3 * 64 * FL_PAD * (int)sizeof(float))

__global__ __launch_bounds__(256) void flash_attn_k(
    const float* __restrict__ qkv, float* __restrict__ out)
{
    extern __shared__ float sm[];
    float* Qs = sm;                  // 64 x 68
    float* Ks = Qs + 64 * FL_PAD;    // 64 x 68
    float* Vs = Ks + 64 * FL_PAD;    // 64 x 68

    const int tid = threadIdx.x;
    const int qi  = tid >> 2;        // 0..63
    const int seg = tid & 3;         // 0..3
    const int q0  = blockIdx.x * 64;
    const int bh  = blockIdx.y;
    const int b   = bh >> 4;
    const int h   = bh & 15;

    const float* qbase = qkv + ((size_t)(b * SS + q0)) * 3072 + h * HD;
    // load Q tile
    for (int l = tid; l < 64 * 64; l += 256) {
        int r = l >> 6, c = l & 63;
        Qs[r * FL_PAD + c] = qbase[(size_t)r * 3072 + c];
    }

    float rm = -1e30f, rl = 0.f;
    float o[16];
#pragma unroll
    for (int jj = 0; jj < 16; ++jj) o[jj] = 0.f;

    for (int k0 = 0; k0 <= q0; k0 += 64) {
        __syncthreads();   // protect Ks/Vs reuse (and first-iter Qs visibility)
        const float* kbase = qkv + ((size_t)(b * SS + k0)) * 3072 + 1024 + h * HD;
        const float* vbase = qkv + ((size_t)(b * SS + k0)) * 3072 + 2048 + h * HD;
        for (int l = tid; l < 64 * 64; l += 256) {
            int r = l >> 6, c = l & 63;
            Ks[r * FL_PAD + c] = kbase[(size_t)r * 3072 + c];
            Vs[r * FL_PAD + c] = vbase[(size_t)r * 3072 + c];
        }
        __syncthreads();

        // scores: sv[jj] = Q[qi,:] . K[seg+4jj,:]
        float sv[16];
#pragma unroll
        for (int jj = 0; jj < 16; ++jj) sv[jj] = 0.f;
#pragma unroll
        for (int d = 0; d < 64; d += 4) {
            float4 q4 = *(const float4*)&Qs[qi * FL_PAD + d];
#pragma unroll
            for (int jj = 0; jj < 16; ++jj) {
                float4 k4 = *(const float4*)&Ks[(seg + 4 * jj) * FL_PAD + d];
                sv[jj] += q4.x * k4.x + q4.y * k4.y + q4.z * k4.z + q4.w * k4.w;
            }
        }
        float tm = -1e30f;
#pragma unroll
        for (int jj = 0; jj < 16; ++jj) {
            sv[jj] *= 0.125f;                       // hd^-0.5
            if (k0 + seg + 4 * jj > q0 + qi) sv[jj] = -1e30f;
            tm = fmaxf(tm, sv[jj]);
        }
        // max over the 4-lane group
        tm = fmaxf(tm, __shfl_xor_sync(0xffffffffu, tm, 1));
        tm = fmaxf(tm, __shfl_xor_sync(0xffffffffu, tm, 2));

        float mnew = fmaxf(rm, tm);
        float corr = __expf(rm - mnew);
        float psum = 0.f;
#pragma unroll
        for (int jj = 0; jj < 16; ++jj) {
            sv[jj] = __expf(sv[jj] - mnew);         // now holds P
            psum += sv[jj];
        }
        psum += __shfl_xor_sync(0xffffffffu, psum, 1);
        psum += __shfl_xor_sync(0xffffffffu, psum, 2);
        rl = rl * corr + psum;
        rm = mnew;
#pragma unroll
        for (int jj = 0; jj < 16; ++jj) o[jj] *= corr;

        // O[qi, seg*16+jj] += sum_j P[qi,j] * V[j, seg*16+jj]
#pragma unroll
        for (int jq = 0; jq < 16; ++jq) {
#pragma unroll
            for (int s = 0; s < 4; ++s) {
                float p = __shfl_sync(0xffffffffu, sv[jq], s, 4);
                const float4* vr = (const float4*)&Vs[(jq * 4 + s) * FL_PAD + seg * 16];
                float4 v0 = vr[0], v1 = vr[1], v2 = vr[2], v3 = vr[3];
                o[0]  += p * v0.x; o[1]  += p * v0.y; o[2]  += p * v0.z; o[3]  += p * v0.w;
                o[4]  += p * v1.x; o[5]  += p * v1.y; o[6]  += p * v1.z; o[7]  += p * v1.w;
                o[8]  += p * v2.x; o[9]  += p * v2.y; o[10] += p * v2.z; o[11] += p * v2.w;
                o[12] += p * v3.x; o[13] += p * v3.y; o[14] += p * v3.z; o[15] += p * v3.w;
            }
        }
    }

    float inv = 1.0f / rl;
    float* op = out + ((size_t)(b * SS + q0 + qi)) * DD + h * HD + seg * 16;
    float4 r;
    r = make_float4(o[0] * inv,  o[1] * inv,  o[2] * inv,  o[3] * inv);  ((float4*)op)[0] = r;
    r = make_float4(o[4] * inv,  o[5] * inv,  o[6] * inv,  o[7] * inv);  ((float4*)op)[1] = r;
    r = make_float4(o[8] * inv,  o[9] * inv,  o[10] * inv, o[11] * inv); ((float4*)op)[2] = r;
    r = make_float4(o[12] * inv, o[13] * inv, o[14] * inv, o[15] * inv); ((float4*)op)[3] = r;
}

// ---------------------------------------------------------------------------
// LayerNorm over D=1024, one block (256 thr) per row, float4 per thread.
// ---------------------------------------------------------------------------
__global__ __launch_bounds__(256) void layernorm_k(
    const float* __restrict__ in, const float* __restrict__ w,
    const float* __restrict__ b, float* __restrict__ out)
{
    __shared__ float red[8];
    __shared__ float bval;
    const int tid = threadIdx.x;
    const size_t base = (size_t)blockIdx.x * DD;

    float4 v = ((const float4*)(in + base))[tid];
    float s = v.x + v.y + v.z + v.w;
#pragma unroll
    for (int off = 16; off; off >>= 1) s += __shfl_xor_sync(0xffffffffu, s, off);
    if ((tid & 31) == 0) red[tid >> 5] = s;
    __syncthreads();
    if (tid == 0) {
        float t = 0.f;
#pragma unroll
        for (int i = 0; i < 8; ++i) t += red[i];
        bval = t * (1.0f / DD);
    }
    __syncthreads();
    const float mu = bval;
    __syncthreads();

    float dx = v.x - mu, dy = v.y - mu, dz = v.z - mu, dw = v.w - mu;
    float q = dx * dx + dy * dy + dz * dz + dw * dw;
#pragma unroll
    for (int off = 16; off; off >>= 1) q += __shfl_xor_sync(0xffffffffu, q, off);
    if ((tid & 31) == 0) red[tid >> 5] = q;
    __syncthreads();
    if (tid == 0) {
        float t = 0.f;
#pragma unroll
        for (int i = 0; i < 8; ++i) t += red[i];
        bval = t * (1.0f / DD);
    }
    __syncthreads();
    const float inv = rsqrtf(bval + 1e-5f);

    float4 w4 = ((const float4*)w)[tid];
    float4 b4 = ((const float4*)b)[tid];
    float4 r = make_float4(dx * inv * w4.x + b4.x,
                           dy * inv * w4.y + b4.y,
                           dz * inv * w4.z + b4.z,
                           dw * inv * w4.w + b4.w);
    ((float4*)(out + base))[tid] = r;
}

// ---------------------------------------------------------------------------
// Launch
// ---------------------------------------------------------------------------
extern "C" void kernel_launch(void* const* d_in, const int* in_sizes, int n_in,
                              void* d_out, int out_size)
{
    const float* x     = (const float*)d_in[0];
    const float* qkv_w = (const float*)d_in[1];
    const float* qkv_b = (const float*)d_in[2];
    const float* out_w = (const float*)d_in[3];
    const float* out_b = (const float*)d_in[4];
    const float* w1    = (const float*)d_in[5];
    const float* b1    = (const float*)d_in[6];
    const float* w2    = (const float*)d_in[7];
    const float* b2    = (const float*)d_in[8];
    const float* ln1w  = (const float*)d_in[9];
    const float* ln1b  = (const float*)d_in[10];
    const float* ln2w  = (const float*)d_in[11];
    const float* ln2b  = (const float*)d_in[12];
    // d_in[13] = attn_mask (causal, hardcoded), d_in[14] = num_heads (16)

    float* outp = (float*)d_out;
    float* kdst = outp + (size_t)MTOK * DD;
    float* vdst = outp + (size_t)2 * MTOK * DD;

    float *qkv, *attn, *h1pre, *h1, *mid, *h2pre;
    cudaGetSymbolAddress((void**)&qkv,   g_qkv);
    cudaGetSymbolAddress((void**)&attn,  g_attn);
    cudaGetSymbolAddress((void**)&h1pre, g_h1pre);
    cudaGetSymbolAddress((void**)&h1,    g_h1);
    cudaGetSymbolAddress((void**)&mid,   g_mid);
    cudaGetSymbolAddress((void**)&h2pre, g_h2pre);

    cudaFuncSetAttribute(flash_attn_k,
                         cudaFuncAttributeMaxDynamicSharedMemorySize, FLASH_SMEM);

    // 1) QKV projection: [4096,1024] @ [3072,1024]^T -> [4096,3072]
    sgemm_k<<<dim3(3072 / 128, MTOK / 128), 256>>>(x, qkv_w, qkv_b, nullptr, qkv,
                                                   MTOK, 3 * DD, DD, 0);
    // 2) k/v caches straight to d_out
    copy_kv_k<<<(MTOK * (DD / 4)) / 256, 256>>>(qkv, kdst, vdst);
    // 3) causal flash attention -> attn [4096,1024]
    flash_attn_k<<<dim3(SS / 64, BB * HH), 256, FLASH_SMEM>>>(qkv, attn);
    // 4) out projection + residual x -> h1pre
    sgemm_k<<<dim3(DD / 128, MTOK / 128), 256>>>(attn, out_w, out_b, x, h1pre,
                                                 MTOK, DD, DD, 0);
    // 5) LN1 -> h1
    layernorm_k<<<MTOK, 256>>>(h1pre, ln1w, ln1b, h1);
    // 6) MLP up + ReLU -> mid [4096,4096]
    sgemm_k<<<dim3(FF_DIM / 128, MTOK / 128), 256>>>(h1, w1, b1, nullptr, mid,
                                                     MTOK, FF_DIM, DD, 1);
    // 7) MLP down + residual h1 -> h2pre
    sgemm_k<<<dim3(DD / 128, MTOK / 128), 256>>>(mid, w2, b2, h1, h2pre,
                                                 MTOK, DD, FF_DIM, 0);
    // 8) LN2 -> out
    layernorm_k<<<MTOK, 256>>>(h2pre, ln2w, ln2b, outp);
}

// round 3
// speedup vs baseline: 1.3954x; 1.3954x over previous
#include <cuda_runtime.h>
#include <cuda_bf16.h>
#include <cstdint>

// Problem constants: B=2, S=2048, D=1024, H=16, hd=64, FF=4096
#define BB 2
#define SS 2048
#define DD 1024
#define HH 16
#define HD 64
#define FF_DIM 4096
#define MTOK (BB*SS)          // 4096 rows

typedef __nv_bfloat16 bf16;

// ---------------------------------------------------------------------------
// Scratch (device globals; no allocation allowed)
// ---------------------------------------------------------------------------
__device__ float g_qkv[(size_t)MTOK * 3 * DD];   // [4096, 3072]
__device__ float g_attn[(size_t)MTOK * DD];
__device__ float g_h1pre[(size_t)MTOK * DD];
__device__ float g_h1[(size_t)MTOK * DD];
__device__ float g_h2pre[(size_t)MTOK * DD];

// hi/lo bf16 split buffers
__device__ bf16 g_xh[(size_t)MTOK * DD],      g_xl[(size_t)MTOK * DD];
__device__ bf16 g_ah[(size_t)MTOK * DD],      g_al[(size_t)MTOK * DD];
__device__ bf16 g_h1h[(size_t)MTOK * DD],     g_h1l[(size_t)MTOK * DD];
__device__ bf16 g_midh[(size_t)MTOK * FF_DIM], g_midl[(size_t)MTOK * FF_DIM];
__device__ bf16 g_wqh[(size_t)3 * DD * DD],   g_wql[(size_t)3 * DD * DD];
__device__ bf16 g_owh[(size_t)DD * DD],       g_owl[(size_t)DD * DD];
__device__ bf16 g_w1h[(size_t)FF_DIM * DD],   g_w1l[(size_t)FF_DIM * DD];
__device__ bf16 g_w2h[(size_t)DD * FF_DIM],   g_w2l[(size_t)DD * FF_DIM];

// ---------------------------------------------------------------------------
// Warp-MMA helpers (sm_80+ features only — legal on base sm_103 target)
// ---------------------------------------------------------------------------
__device__ __forceinline__ uint32_t smem_u32(const void* p) {
    uint32_t a;
    asm("{ .reg .u64 t; cvta.to.shared.u64 t, %1; cvt.u32.u64 %0, t; }"
        : "=r"(a) : "l"(p));
    return a;
}
__device__ __forceinline__ void ldsm4(uint32_t* r, uint32_t a) {
    asm volatile("ldmatrix.sync.aligned.m8n8.x4.shared.b16 {%0,%1,%2,%3}, [%4];"
                 : "=r"(r[0]), "=r"(r[1]), "=r"(r[2]), "=r"(r[3]) : "r"(a));
}
__device__ __forceinline__ void ldsm2(uint32_t* r, uint32_t a) {
    asm volatile("ldmatrix.sync.aligned.m8n8.x2.shared.b16 {%0,%1}, [%2];"
                 : "=r"(r[0]), "=r"(r[1]) : "r"(a));
}
__device__ __forceinline__ void mma16816(float* c, const uint32_t* a, const uint32_t* b) {
    asm volatile(
        "mma.sync.aligned.m16n8k16.row.col.f32.bf16.bf16.f32 "
        "{%0,%1,%2,%3}, {%4,%5,%6,%7}, {%8,%9}, {%0,%1,%2,%3};"
        : "+f"(c[0]), "+f"(c[1]), "+f"(c[2]), "+f"(c[3])
        : "r"(a[0]), "r"(a[1]), "r"(a[2]), "r"(a[3]), "r"(b[0]), "r"(b[1]));
}
#define CP16(dst, src) \
    asm volatile("cp.async.cg.shared.global [%0], [%1], 16;" :: "r"(dst), "l"(src) : "memory")
#define CP_COMMIT() asm volatile("cp.async.commit_group;" ::: "memory")
#define CP_WAIT1()  asm volatile("cp.async.wait_group 1;" ::: "memory")
#define CP_WAIT0()  asm volatile("cp.async.wait_group 0;" ::: "memory")

// ---------------------------------------------------------------------------
// Split-bf16 tensor-core GEMM:
//   C[M,N] = (Ah+Al)[M,K] @ (Wh+Wl)[N,K]^T + bias  (+res) (+relu)
// 3-term: Ah*Wh + Ah*Wl + Al*Wh into one fp32 accumulator.
// 128x128 CTA tile, 8 warps (2x4), warp tile 64x32, K-stage 32, double buffer.
// Smem per stage: Ah|Al|Wh|Wl each 128x32 bf16 (8KB) = 32KB; 2 stages = 64KB.
// Swizzle<2,3,3>: 16B chunk c at row r stored at chunk (c ^ (r&3)).
// ---------------------------------------------------------------------------
#define GEMM_SMEM (2 * 32768)

__global__ __launch_bounds__(256) void gemm_mma(
    const bf16* __restrict__ Ah, const bf16* __restrict__ Al,
    const bf16* __restrict__ Wh, const bf16* __restrict__ Wl,
    const float* __restrict__ bias, const float* __restrict__ res,
    float* __restrict__ C, bf16* __restrict__ Chi, bf16* __restrict__ Clo,
    int M, int N, int K, int relu)
{
    extern __shared__ char dsm[];
    const uint32_t sb = smem_u32(dsm);

    const int tid = threadIdx.x;
    const int lid = tid & 31;
    const int wid = tid >> 5;
    const int wm = wid & 1;          // 2 warps in M
    const int wn = wid >> 1;         // 4 warps in N
    const int bm = blockIdx.y * 128, bn = blockIdx.x * 128;

    const bf16* g0 = Ah + (size_t)bm * K;
    const bf16* g1 = Al + (size_t)bm * K;
    const bf16* g2 = Wh + (size_t)bn * K;
    const bf16* g3 = Wl + (size_t)bn * K;

    float acc[4][4][4];
#pragma unroll
    for (int i = 0; i < 4; ++i)
#pragma unroll
        for (int j = 0; j < 4; ++j)
#pragma unroll
            for (int k = 0; k < 4; ++k) acc[i][j][k] = 0.f;

    const int NC = K >> 5;           // K chunks of 32

    // ---- stage loader ----
    auto load_stage = [&](int stage, int kk) {
        const uint32_t stb = sb + (uint32_t)stage * 32768u;
        const bf16* gs[4] = { g0, g1, g2, g3 };
#pragma unroll
        for (int t4 = 0; t4 < 4; ++t4) {
            const uint32_t tb = stb + (uint32_t)t4 * 8192u;
            const bf16* g = gs[t4] + kk;
#pragma unroll
            for (int j = 0; j < 2; ++j) {
                const int idx = tid * 2 + j;        // 0..511
                const int row = idx >> 2;
                const int c4  = idx & 3;
                const uint32_t dst = tb + (uint32_t)row * 64u
                                   + (uint32_t)((c4 ^ (row & 3)) << 4);
                CP16(dst, (const char*)(g + (size_t)row * K + c4 * 8));
            }
        }
        CP_COMMIT();
    };

    load_stage(0, 0);

    // fragment addresses (per-lane constants)
    const int lrow = lid & 7;
    const int sub  = lid >> 3;               // 0..3
    const int aro  = (sub & 1) * 8 + lrow;   // A row offset within 16
    const int aco  = sub >> 1;               // A k-chunk offset (0/1)
    const int bro  = lid & 7;                // B row (within 8), lanes 0..15 used
    const int bco  = (lid >> 3) & 1;         // B k-chunk offset

    for (int c = 0; c < NC; ++c) {
        if (c + 1 < NC) { load_stage((c + 1) & 1, (c + 1) << 5); CP_WAIT1(); }
        else            { CP_WAIT0(); }
        __syncthreads();

        const uint32_t stb = sb + (uint32_t)(c & 1) * 32768u;
        const uint32_t aB = stb;              // Ah
        const uint32_t wB = stb + 16384u;     // Wh

#pragma unroll
        for (int ks = 0; ks < 2; ++ks) {
            uint32_t ah[4][4], al[4][4], bh[4][2], bl[4][2];
#pragma unroll
            for (int mt = 0; mt < 4; ++mt) {
                const int r = wm * 64 + mt * 16 + aro;
                const int ch = (ks * 2 + aco) ^ (aro & 3);
                const uint32_t ad = aB + (uint32_t)r * 64u + (uint32_t)(ch << 4);
                ldsm4(ah[mt], ad);
                ldsm4(al[mt], ad + 8192u);
            }
#pragma unroll
            for (int nt = 0; nt < 4; ++nt) {
                const int r = wn * 32 + nt * 8 + bro;
                const int ch = (ks * 2 + bco) ^ (bro & 3);
                const uint32_t bd = wB + (uint32_t)r * 64u + (uint32_t)(ch << 4);
                ldsm2(bh[nt], bd);
                ldsm2(bl[nt], bd + 8192u);
            }
#pragma unroll
            for (int mt = 0; mt < 4; ++mt)
#pragma unroll
                for (int nt = 0; nt < 4; ++nt) {
                    mma16816(acc[mt][nt], ah[mt], bh[nt]);
                    mma16816(acc[mt][nt], ah[mt], bl[nt]);
                    mma16816(acc[mt][nt], al[mt], bh[nt]);
                }
        }
        __syncthreads();
    }

    // ---- epilogue ----
    const int l4 = lid >> 2;
    const int l2 = (lid & 3) * 2;
#pragma unroll
    for (int mt = 0; mt < 4; ++mt) {
#pragma unroll
        for (int nt = 0; nt < 4; ++nt) {
            const int col = bn + wn * 32 + nt * 8 + l2;
#pragma unroll
            for (int half = 0; half < 2; ++half) {
                const int row = bm + wm * 64 + mt * 16 + l4 + half * 8;
                float v0 = acc[mt][nt][2 * half + 0];
                float v1 = acc[mt][nt][2 * half + 1];
                v0 += bias[col]; v1 += bias[col + 1];
                const size_t o = (size_t)row * N + col;
                if (res) { v0 += res[o]; v1 += res[o + 1]; }
                if (relu) { v0 = fmaxf(v0, 0.f); v1 = fmaxf(v1, 0.f); }
                if (C) *(float2*)(C + o) = make_float2(v0, v1);
                if (Chi) {
                    bf16 h0 = __float2bfloat16(v0), h1 = __float2bfloat16(v1);
                    *(__nv_bfloat162*)(Chi + o) = __halves2bfloat162(h0, h1);
                    bf16 l0 = __float2bfloat16(v0 - __bfloat162float(h0));
                    bf16 l1 = __float2bfloat16(v1 - __bfloat162float(h1));
                    *(__nv_bfloat162*)(Clo + o) = __halves2bfloat162(l0, l1);
                }
            }
        }
    }
}

// ---------------------------------------------------------------------------
// fp32 -> (hi, lo) bf16 split
// ---------------------------------------------------------------------------
__global__ __launch_bounds__(256) void cvt_hilo_k(
    const float4* __restrict__ in, __nv_bfloat162* __restrict__ hi,
    __nv_bfloat162* __restrict__ lo, int n4)
{
    int i = blockIdx.x * blockDim.x + threadIdx.x;
    if (i >= n4) return;
    float4 v = in[i];
    bf16 hx = __float2bfloat16(v.x), hy = __float2bfloat16(v.y);
    bf16 hz = __float2bfloat16(v.z), hw = __float2bfloat16(v.w);
    hi[2 * i]     = __halves2bfloat162(hx, hy);
    hi[2 * i + 1] = __halves2bfloat162(hz, hw);
    bf16 lx = __float2bfloat16(v.x - __bfloat162float(hx));
    bf16 ly = __float2bfloat16(v.y - __bfloat162float(hy));
    bf16 lz = __float2bfloat16(v.z - __bfloat162float(hz));
    bf16 lw = __float2bfloat16(v.w - __bfloat162float(hw));
    lo[2 * i]     = __halves2bfloat162(lx, ly);
    lo[2 * i + 1] = __halves2bfloat162(lz, lw);
}

// ---------------------------------------------------------------------------
// k/v cache copy out of packed QKV
// ---------------------------------------------------------------------------
__global__ __launch_bounds__(256) void copy_kv_k(
    const float* __restrict__ qkv, float* __restrict__ kd, float* __restrict__ vd)
{
    int i = blockIdx.x * blockDim.x + threadIdx.x;
    int row = i >> 8;
    int c   = i & 255;
    const float4* src = (const float4*)(qkv + (size_t)row * 3072);
    ((float4*)kd)[i] = src[256 + c];
    ((float4*)vd)[i] = src[512 + c];
}

// ---------------------------------------------------------------------------
// Flash attention, fp32, causal (unchanged)
// ---------------------------------------------------------------------------
#define FL_PAD 68
#define FLASH_SMEM (3 * 64 * FL_PAD * (int)sizeof(float))

__global__ __launch_bounds__(256) void flash_attn_k(
    const float* __restrict__ qkv, float* __restrict__ out)
{
    extern __shared__ float sm[];
    float* Qs = sm;
    float* Ks = Qs + 64 * FL_PAD;
    float* Vs = Ks + 64 * FL_PAD;

    const int tid = threadIdx.x;
    const int qi  = tid >> 2;
    const int seg = tid & 3;
    const int q0  = blockIdx.x * 64;
    const int bh  = blockIdx.y;
    const int b   = bh >> 4;
    const int h   = bh & 15;

    const float* qbase = qkv + ((size_t)(b * SS + q0)) * 3072 + h * HD;
    for (int l = tid; l < 64 * 64; l += 256) {
        int r = l >> 6, c = l & 63;
        Qs[r * FL_PAD + c] = qbase[(size_t)r * 3072 + c];
    }

    float rm = -1e30f, rl = 0.f;
    float o[16];
#pragma unroll
    for (int jj = 0; jj < 16; ++jj) o[jj] = 0.f;

    for (int k0 = 0; k0 <= q0; k0 += 64) {
        __syncthreads();
        const float* kbase = qkv + ((size_t)(b * SS + k0)) * 3072 + 1024 + h * HD;
        const float* vbase = qkv + ((size_t)(b * SS + k0)) * 3072 + 2048 + h * HD;
        for (int l = tid; l < 64 * 64; l += 256) {
            int r = l >> 6, c = l & 63;
            Ks[r * FL_PAD + c] = kbase[(size_t)r * 3072 + c];
            Vs[r * FL_PAD + c] = vbase[(size_t)r * 3072 + c];
        }
        __syncthreads();

        float sv[16];
#pragma unroll
        for (int jj = 0; jj < 16; ++jj) sv[jj] = 0.f;
#pragma unroll
        for (int d = 0; d < 64; d += 4) {
            float4 q4 = *(const float4*)&Qs[qi * FL_PAD + d];
#pragma unroll
            for (int jj = 0; jj < 16; ++jj) {
                float4 k4 = *(const float4*)&Ks[(seg + 4 * jj) * FL_PAD + d];
                sv[jj] += q4.x * k4.x + q4.y * k4.y + q4.z * k4.z + q4.w * k4.w;
            }
        }
        float tm = -1e30f;
#pragma unroll
        for (int jj = 0; jj < 16; ++jj) {
            sv[jj] *= 0.125f;
            if (k0 + seg + 4 * jj > q0 + qi) sv[jj] = -1e30f;
            tm = fmaxf(tm, sv[jj]);
        }
        tm = fmaxf(tm, __shfl_xor_sync(0xffffffffu, tm, 1));
        tm = fmaxf(tm, __shfl_xor_sync(0xffffffffu, tm, 2));

        float mnew = fmaxf(rm, tm);
        float corr = __expf(rm - mnew);
        float psum = 0.f;
#pragma unroll
        for (int jj = 0; jj < 16; ++jj) {
            sv[jj] = __expf(sv[jj] - mnew);
            psum += sv[jj];
        }
        psum += __shfl_xor_sync(0xffffffffu, psum, 1);
        psum += __shfl_xor_sync(0xffffffffu, psum, 2);
        rl = rl * corr + psum;
        rm = mnew;
#pragma unroll
        for (int jj = 0; jj < 16; ++jj) o[jj] *= corr;

#pragma unroll
        for (int jq = 0; jq < 16; ++jq) {
#pragma unroll
            for (int s = 0; s < 4; ++s) {
                float p = __shfl_sync(0xffffffffu, sv[jq], s, 4);
                const float4* vr = (const float4*)&Vs[(jq * 4 + s) * FL_PAD + seg * 16];
                float4 v0 = vr[0], v1 = vr[1], v2 = vr[2], v3 = vr[3];
                o[0]  += p * v0.x; o[1]  += p * v0.y; o[2]  += p * v0.z; o[3]  += p * v0.w;
                o[4]  += p * v1.x; o[5]  += p * v1.y; o[6]  += p * v1.z; o[7]  += p * v1.w;
                o[8]  += p * v2.x; o[9]  += p * v2.y; o[10] += p * v2.z; o[11] += p * v2.w;
                o[12] += p * v3.x; o[13] += p * v3.y; o[14] += p * v3.z; o[15] += p * v3.w;
            }
        }
    }

    float inv = 1.0f / rl;
    float* op = out + ((size_t)(b * SS + q0 + qi)) * DD + h * HD + seg * 16;
    float4 r;
    r = make_float4(o[0] * inv,  o[1] * inv,  o[2] * inv,  o[3] * inv);  ((float4*)op)[0] = r;
    r = make_float4(o[4] * inv,  o[5] * inv,  o[6] * inv,  o[7] * inv);  ((float4*)op)[1] = r;
    r = make_float4(o[8] * inv,  o[9] * inv,  o[10] * inv, o[11] * inv); ((float4*)op)[2] = r;
    r = make_float4(o[12] * inv, o[13] * inv, o[14] * inv, o[15] * inv); ((float4*)op)[3] = r;
}

// ---------------------------------------------------------------------------
// LayerNorm over D=1024, optional fused bf16 hi/lo output
// ---------------------------------------------------------------------------
__global__ __launch_bounds__(256) void layernorm_k(
    const float* __restrict__ in, const float* __restrict__ w,
    const float* __restrict__ b, float* __restrict__ out,
    bf16* __restrict__ ohi, bf16* __restrict__ olo)
{
    __shared__ float red[8];
    __shared__ float bval;
    const int tid = threadIdx.x;
    const size_t base = (size_t)blockIdx.x * DD;

    float4 v = ((const float4*)(in + base))[tid];
    float s = v.x + v.y + v.z + v.w;
#pragma unroll
    for (int off = 16; off; off >>= 1) s += __shfl_xor_sync(0xffffffffu, s, off);
    if ((tid & 31) == 0) red[tid >> 5] = s;
    __syncthreads();
    if (tid == 0) {
        float t = 0.f;
#pragma unroll
        for (int i = 0; i < 8; ++i) t += red[i];
        bval = t * (1.0f / DD);
    }
    __syncthreads();
    const float mu = bval;
    __syncthreads();

    float dx = v.x - mu, dy = v.y - mu, dz = v.z - mu, dw = v.w - mu;
    float q = dx * dx + dy * dy + dz * dz + dw * dw;
#pragma unroll
    for (int off = 16; off; off >>= 1) q += __shfl_xor_sync(0xffffffffu, q, off);
    if ((tid & 31) == 0) red[tid >> 5] = q;
    __syncthreads();
    if (tid == 0) {
        float t = 0.f;
#pragma unroll
        for (int i = 0; i < 8; ++i) t += red[i];
        bval = t * (1.0f / DD);
    }
    __syncthreads();
    const float inv = rsqrtf(bval + 1e-5f);

    float4 w4 = ((const float4*)w)[tid];
    float4 b4 = ((const float4*)b)[tid];
    float4 r = make_float4(dx * inv * w4.x + b4.x,
                           dy * inv * w4.y + b4.y,
                           dz * inv * w4.z + b4.z,
                           dw * inv * w4.w + b4.w);
    ((float4*)(out + base))[tid] = r;
    if (ohi) {
        bf16 hx = __float2bfloat16(r.x), hy = __float2bfloat16(r.y);
        bf16 hz = __float2bfloat16(r.z), hw = __float2bfloat16(r.w);
        *(__nv_bfloat162*)(ohi + base + 4 * tid)     = __halves2bfloat162(hx, hy);
        *(__nv_bfloat162*)(ohi + base + 4 * tid + 2) = __halves2bfloat162(hz, hw);
        bf16 lx = __float2bfloat16(r.x - __bfloat162float(hx));
        bf16 ly = __float2bfloat16(r.y - __bfloat162float(hy));
        bf16 lz = __float2bfloat16(r.z - __bfloat162float(hz));
        bf16 lw = __float2bfloat16(r.w - __bfloat162float(hw));
        *(__nv_bfloat162*)(olo + base + 4 * tid)     = __halves2bfloat162(lx, ly);
        *(__nv_bfloat162*)(olo + base + 4 * tid + 2) = __halves2bfloat162(lz, lw);
    }
}

// ---------------------------------------------------------------------------
// Launch
// ---------------------------------------------------------------------------
static inline void cvt(const float* in, bf16* hi, bf16* lo, size_t n) {
    int n4 = (int)(n / 4);
    cvt_hilo_k<<<(n4 + 255) / 256, 256>>>((const float4*)in,
                                          (__nv_bfloat162*)hi, (__nv_bfloat162*)lo, n4);
}

extern "C" void kernel_launch(void* const* d_in, const int* in_sizes, int n_in,
                              void* d_out, int out_size)
{
    const float* x     = (const float*)d_in[0];
    const float* qkv_w = (const float*)d_in[1];
    const float* qkv_b = (const float*)d_in[2];
    const float* out_w = (const float*)d_in[3];
    const float* out_b = (const float*)d_in[4];
    const float* w1    = (const float*)d_in[5];
    const float* b1    = (const float*)d_in[6];
    const float* w2    = (const float*)d_in[7];
    const float* b2    = (const float*)d_in[8];
    const float* ln1w  = (const float*)d_in[9];
    const float* ln1b  = (const float*)d_in[10];
    const float* ln2w  = (const float*)d_in[11];
    const float* ln2b  = (const float*)d_in[12];

    float* outp = (float*)d_out;
    float* kdst = outp + (size_t)MTOK * DD;
    float* vdst = outp + (size_t)2 * MTOK * DD;

    float *qkv, *attn, *h1pre, *h1, *h2pre;
    bf16 *xh, *xl, *ah, *al, *h1h, *h1l, *midh, *midl;
    bf16 *wqh, *wql, *owh, *owl, *w1h, *w1l, *w2h, *w2l;
    cudaGetSymbolAddress((void**)&qkv,   g_qkv);
    cudaGetSymbolAddress((void**)&attn,  g_attn);
    cudaGetSymbolAddress((void**)&h1pre, g_h1pre);
    cudaGetSymbolAddress((void**)&h1,    g_h1);
    cudaGetSymbolAddress((void**)&h2pre, g_h2pre);
    cudaGetSymbolAddress((void**)&xh,    g_xh);   cudaGetSymbolAddress((void**)&xl, g_xl);
    cudaGetSymbolAddress((void**)&ah,    g_ah);   cudaGetSymbolAddress((void**)&al, g_al);
    cudaGetSymbolAddress((void**)&h1h,   g_h1h);  cudaGetSymbolAddress((void**)&h1l, g_h1l);
    cudaGetSymbolAddress((void**)&midh,  g_midh); cudaGetSymbolAddress((void**)&midl, g_midl);
    cudaGetSymbolAddress((void**)&wqh,   g_wqh);  cudaGetSymbolAddress((void**)&wql, g_wql);
    cudaGetSymbolAddress((void**)&owh,   g_owh);  cudaGetSymbolAddress((void**)&owl, g_owl);
    cudaGetSymbolAddress((void**)&w1h,   g_w1h);  cudaGetSymbolAddress((void**)&w1l, g_w1l);
    cudaGetSymbolAddress((void**)&w2h,   g_w2h);  cudaGetSymbolAddress((void**)&w2l, g_w2l);

    cudaFuncSetAttribute(flash_attn_k,
                         cudaFuncAttributeMaxDynamicSharedMemorySize, FLASH_SMEM);
    cudaFuncSetAttribute(gemm_mma,
                         cudaFuncAttributeMaxDynamicSharedMemorySize, GEMM_SMEM);

    // 0) split weights + x into bf16 hi/lo
    cvt(qkv_w, wqh, wql, (size_t)3 * DD * DD);
    cvt(out_w, owh, owl, (size_t)DD * DD);
    cvt(w1,    w1h, w1l, (size_t)FF_DIM * DD);
    cvt(w2,    w2h, w2l, (size_t)DD * FF_DIM);
    cvt(x,     xh,  xl,  (size_t)MTOK * DD);

    // 1) QKV projection -> qkv fp32 [4096,3072]
    gemm_mma<<<dim3(3072 / 128, MTOK / 128), 256, GEMM_SMEM>>>(
        xh, xl, wqh, wql, qkv_b, nullptr, qkv, nullptr, nullptr,
        MTOK, 3 * DD, DD, 0);
    // 2) k/v caches
    copy_kv_k<<<(MTOK * (DD / 4)) / 256, 256>>>(qkv, kdst, vdst);
    // 3) causal flash attention -> attn fp32
    flash_attn_k<<<dim3(SS / 64, BB * HH), 256, FLASH_SMEM>>>(qkv, attn);
    // 4) split attn
    cvt(attn, ah, al, (size_t)MTOK * DD);
    // 5) out projection + residual x -> h1pre
    gemm_mma<<<dim3(DD / 128, MTOK / 128), 256, GEMM_SMEM>>>(
        ah, al, owh, owl, out_b, x, h1pre, nullptr, nullptr,
        MTOK, DD, DD, 0);
    // 6) LN1 -> h1 fp32 + hi/lo
    layernorm_k<<<MTOK, 256>>>(h1pre, ln1w, ln1b, h1, h1h, h1l);
    // 7) MLP up + ReLU -> mid hi/lo only
    gemm_mma<<<dim3(FF_DIM / 128, MTOK / 128), 256, GEMM_SMEM>>>(
        h1h, h1l, w1h, w1l, b1, nullptr, nullptr, midh, midl,
        MTOK, FF_DIM, DD, 1);
    // 8) MLP down + residual h1 -> h2pre
    gemm_mma<<<dim3(DD / 128, MTOK / 128), 256, GEMM_SMEM>>>(
        midh, midl, w2h, w2l, b2, h1, h2pre, nullptr, nullptr,
        MTOK, DD, FF_DIM, 0);
    // 9) LN2 -> out
    layernorm_k<<<MTOK, 256>>>(h2pre, ln2w, ln2b, outp, nullptr, nullptr);
}

// round 4
// speedup vs baseline: 2.8977x; 2.0767x over previous
#include <cuda_runtime.h>
#include <cuda_bf16.h>
#include <cstdint>

// Problem constants: B=2, S=2048, D=1024, H=16, hd=64, FF=4096
#define BB 2
#define SS 2048
#define DD 1024
#define HH 16
#define HD 64
#define FF_DIM 4096
#define MTOK (BB*SS)          // 4096 rows

typedef __nv_bfloat16 bf16;

// ---------------------------------------------------------------------------
// Scratch (device globals; no allocation allowed)
// ---------------------------------------------------------------------------
__device__ float g_qkv[(size_t)MTOK * 3 * DD];   // [4096, 3072] fp32 (kv cache src)
__device__ bf16 g_qkvh[(size_t)MTOK * 3 * DD], g_qkvl[(size_t)MTOK * 3 * DD];
__device__ float g_h1pre[(size_t)MTOK * DD];
__device__ float g_h1[(size_t)MTOK * DD];
__device__ float g_h2pre[(size_t)MTOK * DD];

__device__ bf16 g_xh[(size_t)MTOK * DD],      g_xl[(size_t)MTOK * DD];
__device__ bf16 g_ah[(size_t)MTOK * DD],      g_al[(size_t)MTOK * DD];   // attn out
__device__ bf16 g_h1h[(size_t)MTOK * DD],     g_h1l[(size_t)MTOK * DD];
__device__ bf16 g_midh[(size_t)MTOK * FF_DIM], g_midl[(size_t)MTOK * FF_DIM];
__device__ bf16 g_wqh[(size_t)3 * DD * DD],   g_wql[(size_t)3 * DD * DD];
__device__ bf16 g_owh[(size_t)DD * DD],       g_owl[(size_t)DD * DD];
__device__ bf16 g_w1h[(size_t)FF_DIM * DD],   g_w1l[(size_t)FF_DIM * DD];
__device__ bf16 g_w2h[(size_t)DD * FF_DIM],   g_w2l[(size_t)DD * FF_DIM];

// ---------------------------------------------------------------------------
// MMA / ldmatrix / cp.async helpers (sm_80+ features, legal on base sm_103)
// ---------------------------------------------------------------------------
__device__ __forceinline__ uint32_t smem_u32(const void* p) {
    uint32_t a;
    asm("{ .reg .u64 t; cvta.to.shared.u64 t, %1; cvt.u32.u64 %0, t; }"
        : "=r"(a) : "l"(p));
    return a;
}
__device__ __forceinline__ void ldsm4(uint32_t* r, uint32_t a) {
    asm volatile("ldmatrix.sync.aligned.m8n8.x4.shared.b16 {%0,%1,%2,%3}, [%4];"
                 : "=r"(r[0]), "=r"(r[1]), "=r"(r[2]), "=r"(r[3]) : "r"(a));
}
__device__ __forceinline__ void ldsm4t(uint32_t* r, uint32_t a) {
    asm volatile("ldmatrix.sync.aligned.m8n8.x4.trans.shared.b16 {%0,%1,%2,%3}, [%4];"
                 : "=r"(r[0]), "=r"(r[1]), "=r"(r[2]), "=r"(r[3]) : "r"(a));
}
__device__ __forceinline__ void mma16816(float* c, const uint32_t* a, const uint32_t* b) {
    asm volatile(
        "mma.sync.aligned.m16n8k16.row.col.f32.bf16.bf16.f32 "
        "{%0,%1,%2,%3}, {%4,%5,%6,%7}, {%8,%9}, {%0,%1,%2,%3};"
        : "+f"(c[0]), "+f"(c[1]), "+f"(c[2]), "+f"(c[3])
        : "r"(a[0]), "r"(a[1]), "r"(a[2]), "r"(a[3]), "r"(b[0]), "r"(b[1]));
}
#define CP16(dst, src) \
    asm volatile("cp.async.cg.shared.global [%0], [%1], 16;" :: "r"(dst), "l"(src) : "memory")
#define CP_COMMIT() asm volatile("cp.async.commit_group;" ::: "memory")
#define CP_WAIT1()  asm volatile("cp.async.wait_group 1;" ::: "memory")
#define CP_WAIT0()  asm volatile("cp.async.wait_group 0;" ::: "memory")

// 128B-row tile addressing: row stride 128B, 16B chunk ch swizzled by row&7.
__device__ __forceinline__ uint32_t tile_addr(uint32_t base, int row, int ch) {
    return base + (uint32_t)row * 128u + (uint32_t)((ch ^ (row & 7)) << 4);
}
__device__ __forceinline__ uint32_t pack_hi(float a, float b) {
    __nv_bfloat162 h = __halves2bfloat162(__float2bfloat16(a), __float2bfloat16(b));
    return *(uint32_t*)&h;
}
__device__ __forceinline__ uint32_t pack_lo(float a, float b) {
    bf16 ha = __float2bfloat16(a), hb = __float2bfloat16(b);
    __nv_bfloat162 l = __halves2bfloat162(__float2bfloat16(a - __bfloat162float(ha)),
                                          __float2bfloat16(b - __bfloat162float(hb)));
    return *(uint32_t*)&l;
}

// ---------------------------------------------------------------------------
// Split-bf16 tensor-core GEMM: C[M,N] = (Ah+Al)@(Wh+Wl)^T + bias (+res)(+relu)
// 128x128 CTA tile, 8 warps (2Mx4N), warp tile 64x32, K-stage 64, 2 stages.
// Tiles: Ah|Al|Wh|Wl each [128][64] bf16 (16KB), 128B rows, conflict-free swz.
// ---------------------------------------------------------------------------
#define GEMM_SMEM (2 * 4 * 16384)   // 128KB

__global__ __launch_bounds__(256) void gemm_mma(
    const bf16* __restrict__ Ah, const bf16* __restrict__ Al,
    const bf16* __restrict__ Wh, const bf16* __restrict__ Wl,
    const float* __restrict__ bias, const float* __restrict__ res,
    float* __restrict__ C, bf16* __restrict__ Chi, bf16* __restrict__ Clo,
    int M, int N, int K, int relu)
{
    extern __shared__ char dsm[];
    const uint32_t sb = smem_u32(dsm);

    const int tid = threadIdx.x;
    const int lid = tid & 31;
    const int wid = tid >> 5;
    const int wm = wid & 1;
    const int wn = wid >> 1;
    const int bm = blockIdx.y * 128, bn = blockIdx.x * 128;

    const bf16* gs[4] = { Ah + (size_t)bm * K, Al + (size_t)bm * K,
                          Wh + (size_t)bn * K, Wl + (size_t)bn * K };

    float acc[4][4][4];
#pragma unroll
    for (int i = 0; i < 4; ++i)
#pragma unroll
        for (int j = 0; j < 4; ++j)
#pragma unroll
            for (int k = 0; k < 4; ++k) acc[i][j][k] = 0.f;

    const int NC = K >> 6;

    auto load_stage = [&](int stage, int kk) {
        const uint32_t stb = sb + (uint32_t)stage * 65536u;
        const int row = tid >> 1;
        const int cb  = (tid & 1) * 4;
#pragma unroll
        for (int t4 = 0; t4 < 4; ++t4) {
            const uint32_t tb = stb + (uint32_t)t4 * 16384u;
            const bf16* g = gs[t4] + kk + (size_t)row * K;
#pragma unroll
            for (int j = 0; j < 4; ++j) {
                const int ch = cb + j;
                CP16(tile_addr(tb, row, ch), (const char*)(g + ch * 8));
            }
        }
        CP_COMMIT();
    };

    load_stage(0, 0);

    const int arow = lid & 15;
    const int achd = lid >> 4;

    for (int c = 0; c < NC; ++c) {
        if (c + 1 < NC) { load_stage((c + 1) & 1, (c + 1) << 6); CP_WAIT1(); }
        else            { CP_WAIT0(); }
        __syncthreads();

        const uint32_t stb = sb + (uint32_t)(c & 1) * 65536u;

#pragma unroll
        for (int ks = 0; ks < 4; ++ks) {
            uint32_t ah[4][4], al[4][4];
#pragma unroll
            for (int mt = 0; mt < 4; ++mt) {
                const int r = wm * 64 + mt * 16 + arow;
                const uint32_t ad = tile_addr(stb, r, ks * 2 + achd);
                ldsm4(ah[mt], ad);
                ldsm4(al[mt], ad + 16384u);
            }
            uint32_t bh[4][2], bl[4][2];
#pragma unroll
            for (int ntp = 0; ntp < 2; ++ntp) {
                const int r = wn * 32 + ntp * 16 + arow;
                const uint32_t bd = tile_addr(stb + 32768u, r, ks * 2 + achd);
                uint32_t t[4], u[4];
                ldsm4(t, bd);
                ldsm4(u, bd + 16384u);
                bh[2 * ntp][0] = t[0]; bh[2 * ntp][1] = t[2];
                bh[2 * ntp + 1][0] = t[1]; bh[2 * ntp + 1][1] = t[3];
                bl[2 * ntp][0] = u[0]; bl[2 * ntp][1] = u[2];
                bl[2 * ntp + 1][0] = u[1]; bl[2 * ntp + 1][1] = u[3];
            }
#pragma unroll
            for (int mt = 0; mt < 4; ++mt)
#pragma unroll
                for (int nt = 0; nt < 4; ++nt) {
                    mma16816(acc[mt][nt], ah[mt], bh[nt]);
                    mma16816(acc[mt][nt], ah[mt], bl[nt]);
                    mma16816(acc[mt][nt], al[mt], bh[nt]);
                }
        }
        __syncthreads();
    }

    const int l4 = lid >> 2;
    const int l2 = (lid & 3) * 2;
#pragma unroll
    for (int mt = 0; mt < 4; ++mt) {
#pragma unroll
        for (int nt = 0; nt < 4; ++nt) {
            const int col = bn + wn * 32 + nt * 8 + l2;
#pragma unroll
            for (int half = 0; half < 2; ++half) {
                const int row = bm + wm * 64 + mt * 16 + l4 + half * 8;
                float v0 = acc[mt][nt][2 * half + 0];
                float v1 = acc[mt][nt][2 * half + 1];
                v0 += bias[col]; v1 += bias[col + 1];
                const size_t o = (size_t)row * N + col;
                if (res) { v0 += res[o]; v1 += res[o + 1]; }
                if (relu) { v0 = fmaxf(v0, 0.f); v1 = fmaxf(v1, 0.f); }
                if (C) *(float2*)(C + o) = make_float2(v0, v1);
                if (Chi) {
                    *(uint32_t*)(Chi + o) = pack_hi(v0, v1);
                    *(uint32_t*)(Clo + o) = pack_lo(v0, v1);
                }
            }
        }
    }
}

// ---------------------------------------------------------------------------
// fp32 -> (hi, lo) bf16 split
// ---------------------------------------------------------------------------
__global__ __launch_bounds__(256) void cvt_hilo_k(
    const float4* __restrict__ in, uint32_t* __restrict__ hi,
    uint32_t* __restrict__ lo, int n4)
{
    int i = blockIdx.x * blockDim.x + threadIdx.x;
    if (i >= n4) return;
    float4 v = in[i];
    hi[2 * i]     = pack_hi(v.x, v.y);
    hi[2 * i + 1] = pack_hi(v.z, v.w);
    lo[2 * i]     = pack_lo(v.x, v.y);
    lo[2 * i + 1] = pack_lo(v.z, v.w);
}

// ---------------------------------------------------------------------------
// k/v cache copy out of packed QKV (fp32)
// ---------------------------------------------------------------------------
__global__ __launch_bounds__(256) void copy_kv_k(
    const float* __restrict__ qkv, float* __restrict__ kd, float* __restrict__ vd)
{
    int i = blockIdx.x * blockDim.x + threadIdx.x;
    int row = i >> 8;
    int c   = i & 255;
    const float4* src = (const float4*)(qkv + (size_t)row * 3072);
    ((float4*)kd)[i] = src[256 + c];
    ((float4*)vd)[i] = src[512 + c];
}

// ---------------------------------------------------------------------------
// Tensor-core flash attention, causal, split-bf16 (3-term), online softmax.
// CTA = 128 queries of one (b,h); 8 warps x 16 query rows; K-blocks of 64.
// Smem: Qh|Ql [128][64] (32KB) + 2 bufs x (Kh|Kl|Vh|Vl [64][64]) (64KB).
// Emits attn output directly as hi/lo bf16 [4096][1024].
// ---------------------------------------------------------------------------
#define FA_SMEM (32768 + 2 * 32768)

__global__ __launch_bounds__(256) void flash_mma_k(
    const bf16* __restrict__ qh, const bf16* __restrict__ ql,
    bf16* __restrict__ oh, bf16* __restrict__ ol)
{
    extern __shared__ char dsm[];
    const uint32_t sb = smem_u32(dsm);
    const uint32_t Qh = sb, Ql = sb + 16384u;

    const int tid = threadIdx.x;
    const int lid = tid & 31;
    const int w   = tid >> 5;
    const int q0  = blockIdx.x * 128;
    const int b   = blockIdx.y >> 4;
    const int h   = blockIdx.y & 15;
    const size_t grow = (size_t)(b * SS);

    // ---- loaders ----
    auto load_q = [&]() {
        const int row = tid >> 1;
        const int cb  = (tid & 1) * 4;
        const size_t src = (grow + q0 + row) * 3072 + h * HD;
#pragma unroll
        for (int j = 0; j < 4; ++j) {
            const int ch = cb + j;
            CP16(tile_addr(Qh, row, ch), (const char*)(qh + src + ch * 8));
            CP16(tile_addr(Ql, row, ch), (const char*)(ql + src + ch * 8));
        }
    };
    auto load_kv = [&](int buf, int k0) {
        const uint32_t bbase = sb + 32768u + (uint32_t)buf * 32768u;
        const int row = tid >> 2;
        const int cb  = (tid & 3) * 2;
        const size_t srcK = (grow + k0 + row) * 3072 + 1024 + h * HD;
        const size_t srcV = srcK + 1024;
#pragma unroll
        for (int j = 0; j < 2; ++j) {
            const int ch = cb + j;
            const uint32_t off = tile_addr(0, row, ch);
            CP16(bbase + off,           (const char*)(qh + srcK + ch * 8));
            CP16(bbase + 8192u + off,   (const char*)(ql + srcK + ch * 8));
            CP16(bbase + 16384u + off,  (const char*)(qh + srcV + ch * 8));
            CP16(bbase + 24576u + off,  (const char*)(ql + srcV + ch * 8));
        }
    };

    load_q();
    load_kv(0, 0);
    CP_COMMIT();

    const int nblk = q0 / 64 + 2;
    const int arow = lid & 15;
    const int achd = lid >> 4;

    uint32_t qfh[4][4], qfl[4][4];
    float of[8][4];
#pragma unroll
    for (int i = 0; i < 8; ++i)
#pragma unroll
        for (int j = 0; j < 4; ++j) of[i][j] = 0.f;
    float m0 = -1e30f, m1 = -1e30f, l0 = 0.f, l1 = 0.f;

    const int row_lo = lid >> 2;          // local row within 16 (and +8)

    for (int c = 0; c < nblk; ++c) {
        if (c + 1 < nblk) { load_kv((c + 1) & 1, (c + 1) * 64); CP_COMMIT(); CP_WAIT1(); }
        else              { CP_WAIT0(); }
        __syncthreads();

        if (c == 0) {
            // hoist Q fragments (row = w*16 + arow)
#pragma unroll
            for (int ks = 0; ks < 4; ++ks) {
                const uint32_t ad = tile_addr(Qh, w * 16 + arow, ks * 2 + achd);
                ldsm4(qfh[ks], ad);
                ldsm4(qfl[ks], ad + 16384u);
            }
        }

        const uint32_t kb = sb + 32768u + (uint32_t)(c & 1) * 32768u;
        const int k0 = c * 64;

        // ---- scores S[16][64] ----
        float sf[8][4];
#pragma unroll
        for (int i = 0; i < 8; ++i)
#pragma unroll
            for (int j = 0; j < 4; ++j) sf[i][j] = 0.f;

#pragma unroll
        for (int ks = 0; ks < 4; ++ks) {
            uint32_t bh[8][2], bl[8][2];
#pragma unroll
            for (int ntp = 0; ntp < 4; ++ntp) {
                const uint32_t bd = tile_addr(kb, ntp * 16 + arow, ks * 2 + achd);
                uint32_t t[4], u[4];
                ldsm4(t, bd);
                ldsm4(u, bd + 8192u);
                bh[2 * ntp][0] = t[0]; bh[2 * ntp][1] = t[2];
                bh[2 * ntp + 1][0] = t[1]; bh[2 * ntp + 1][1] = t[3];
                bl[2 * ntp][0] = u[0]; bl[2 * ntp][1] = u[2];
                bl[2 * ntp + 1][0] = u[1]; bl[2 * ntp + 1][1] = u[3];
            }
#pragma unroll
            for (int nt = 0; nt < 8; ++nt) {
                mma16816(sf[nt], qfh[ks], bh[nt]);
                mma16816(sf[nt], qfh[ks], bl[nt]);
                mma16816(sf[nt], qfl[ks], bh[nt]);
            }
        }

        // ---- scale + causal mask ----
        const int grow0 = q0 + w * 16 + row_lo;      // global query row (idx 0,1)
        const int grow1 = grow0 + 8;
        const bool need_mask = (k0 + 63 > q0 + w * 16);
#pragma unroll
        for (int nt = 0; nt < 8; ++nt) {
            const int col = k0 + nt * 8 + 2 * (lid & 3);
#pragma unroll
            for (int j = 0; j < 4; ++j) sf[nt][j] *= 0.125f;
            if (need_mask) {
                if (col     > grow0) sf[nt][0] = -1e30f;
                if (col + 1 > grow0) sf[nt][1] = -1e30f;
                if (col     > grow1) sf[nt][2] = -1e30f;
                if (col + 1 > grow1) sf[nt][3] = -1e30f;
            }
        }

        // ---- online softmax ----
        float tm0 = -1e30f, tm1 = -1e30f;
#pragma unroll
        for (int nt = 0; nt < 8; ++nt) {
            tm0 = fmaxf(tm0, fmaxf(sf[nt][0], sf[nt][1]));
            tm1 = fmaxf(tm1, fmaxf(sf[nt][2], sf[nt][3]));
        }
        tm0 = fmaxf(tm0, __shfl_xor_sync(0xffffffffu, tm0, 1));
        tm0 = fmaxf(tm0, __shfl_xor_sync(0xffffffffu, tm0, 2));
        tm1 = fmaxf(tm1, __shfl_xor_sync(0xffffffffu, tm1, 1));
        tm1 = fmaxf(tm1, __shfl_xor_sync(0xffffffffu, tm1, 2));

        const float mn0 = fmaxf(m0, tm0), mn1 = fmaxf(m1, tm1);
        const float cr0 = __expf(m0 - mn0), cr1 = __expf(m1 - mn1);
        m0 = mn0; m1 = mn1;

        float ps0 = 0.f, ps1 = 0.f;
#pragma unroll
        for (int nt = 0; nt < 8; ++nt) {
            sf[nt][0] = __expf(sf[nt][0] - mn0);
            sf[nt][1] = __expf(sf[nt][1] - mn0);
            sf[nt][2] = __expf(sf[nt][2] - mn1);
            sf[nt][3] = __expf(sf[nt][3] - mn1);
            ps0 += sf[nt][0] + sf[nt][1];
            ps1 += sf[nt][2] + sf[nt][3];
        }
        ps0 += __shfl_xor_sync(0xffffffffu, ps0, 1);
        ps0 += __shfl_xor_sync(0xffffffffu, ps0, 2);
        ps1 += __shfl_xor_sync(0xffffffffu, ps1, 1);
        ps1 += __shfl_xor_sync(0xffffffffu, ps1, 2);
        l0 = l0 * cr0 + ps0;
        l1 = l1 * cr1 + ps1;
#pragma unroll
        for (int nt = 0; nt < 8; ++nt) {
            of[nt][0] *= cr0; of[nt][1] *= cr0;
            of[nt][2] *= cr1; of[nt][3] *= cr1;
        }

        // ---- P -> bf16 hi/lo A-fragments (C layout == A layout) ----
        uint32_t pah[4][4], pal[4][4];
#pragma unroll
        for (int kk = 0; kk < 4; ++kk) {
            pah[kk][0] = pack_hi(sf[2 * kk][0], sf[2 * kk][1]);
            pah[kk][1] = pack_hi(sf[2 * kk][2], sf[2 * kk][3]);
            pah[kk][2] = pack_hi(sf[2 * kk + 1][0], sf[2 * kk + 1][1]);
            pah[kk][3] = pack_hi(sf[2 * kk + 1][2], sf[2 * kk + 1][3]);
            pal[kk][0] = pack_lo(sf[2 * kk][0], sf[2 * kk][1]);
            pal[kk][1] = pack_lo(sf[2 * kk][2], sf[2 * kk][3]);
            pal[kk][2] = pack_lo(sf[2 * kk + 1][0], sf[2 * kk + 1][1]);
            pal[kk][3] = pack_lo(sf[2 * kk + 1][2], sf[2 * kk + 1][3]);
        }

        // ---- O += P @ V ----
        const uint32_t vb = kb + 16384u;
#pragma unroll
        for (int ks = 0; ks < 4; ++ks) {
            uint32_t vh[8][2], vl[8][2];
#pragma unroll
            for (int ntp = 0; ntp < 4; ++ntp) {
                const int krow = ks * 16 + arow;
                const uint32_t vd = tile_addr(vb, krow, ntp * 2 + achd);
                uint32_t t[4], u[4];
                ldsm4t(t, vd);
                ldsm4t(u, vd + 8192u);
                vh[2 * ntp][0] = t[0]; vh[2 * ntp][1] = t[1];
                vh[2 * ntp + 1][0] = t[2]; vh[2 * ntp + 1][1] = t[3];
                vl[2 * ntp][0] = u[0]; vl[2 * ntp][1] = u[1];
                vl[2 * ntp + 1][0] = u[2]; vl[2 * ntp + 1][1] = u[3];
            }
#pragma unroll
            for (int nt = 0; nt < 8; ++nt) {
                mma16816(of[nt], pah[ks], vh[nt]);
                mma16816(of[nt], pah[ks], vl[nt]);
                mma16816(of[nt], pal[ks], vh[nt]);
            }
        }
        __syncthreads();
    }

    // ---- normalize + store hi/lo bf16 ----
    const float iv0 = 1.0f / l0, iv1 = 1.0f / l1;
    const size_t r0 = (grow + q0 + w * 16 + row_lo) * DD + h * HD;
    const size_t r1 = r0 + 8 * DD;
#pragma unroll
    for (int nt = 0; nt < 8; ++nt) {
        const int cofs = nt * 8 + 2 * (lid & 3);
        float v0 = of[nt][0] * iv0, v1 = of[nt][1] * iv0;
        float v2 = of[nt][2] * iv1, v3 = of[nt][3] * iv1;
        *(uint32_t*)(oh + r0 + cofs) = pack_hi(v0, v1);
        *(uint32_t*)(ol + r0 + cofs) = pack_lo(v0, v1);
        *(uint32_t*)(oh + r1 + cofs) = pack_hi(v2, v3);
        *(uint32_t*)(ol + r1 + cofs) = pack_lo(v2, v3);
    }
}

// ---------------------------------------------------------------------------
// LayerNorm over D=1024, optional fused bf16 hi/lo output
// ---------------------------------------------------------------------------
__global__ __launch_bounds__(256) void layernorm_k(
    const float* __restrict__ in, const float* __restrict__ w,
    const float* __restrict__ b, float* __restrict__ out,
    bf16* __restrict__ ohi, bf16* __restrict__ olo)
{
    __shared__ float red[8];
    __shared__ float bval;
    const int tid = threadIdx.x;
    const size_t base = (size_t)blockIdx.x * DD;

    float4 v = ((const float4*)(in + base))[tid];
    float s = v.x + v.y + v.z + v.w;
#pragma unroll
    for (int off = 16; off; off >>= 1) s += __shfl_xor_sync(0xffffffffu, s, off);
    if ((tid & 31) == 0) red[tid >> 5] = s;
    __syncthreads();
    if (tid == 0) {
        float t = 0.f;
#pragma unroll
        for (int i = 0; i < 8; ++i) t += red[i];
        bval = t * (1.0f / DD);
    }
    __syncthreads();
    const float mu = bval;
    __syncthreads();

    float dx = v.x - mu, dy = v.y - mu, dz = v.z - mu, dw = v.w - mu;
    float q = dx * dx + dy * dy + dz * dz + dw * dw;
#pragma unroll
    for (int off = 16; off; off >>= 1) q += __shfl_xor_sync(0xffffffffu, q, off);
    if ((tid & 31) == 0) red[tid >> 5] = q;
    __syncthreads();
    if (tid == 0) {
        float t = 0.f;
#pragma unroll
        for (int i = 0; i < 8; ++i) t += red[i];
        bval = t * (1.0f / DD);
    }
    __syncthreads();
    const float inv = rsqrtf(bval + 1e-5f);

    float4 w4 = ((const float4*)w)[tid];
    float4 b4 = ((const float4*)b)[tid];
    float4 r = make_float4(dx * inv * w4.x + b4.x,
                           dy * inv * w4.y + b4.y,
                           dz * inv * w4.z + b4.z,
                           dw * inv * w4.w + b4.w);
    ((float4*)(out + base))[tid] = r;
    if (ohi) {
        *(uint32_t*)(ohi + base + 4 * tid)     = pack_hi(r.x, r.y);
        *(uint32_t*)(ohi + base + 4 * tid + 2) = pack_hi(r.z, r.w);
        *(uint32_t*)(olo + base + 4 * tid)     = pack_lo(r.x, r.y);
        *(uint32_t*)(olo + base + 4 * tid + 2) = pack_lo(r.z, r.w);
    }
}

// ---------------------------------------------------------------------------
// Launch
// ---------------------------------------------------------------------------
static inline void cvt(const float* in, bf16* hi, bf16* lo, size_t n) {
    int n4 = (int)(n / 4);
    cvt_hilo_k<<<(n4 + 255) / 256, 256>>>((const float4*)in,
                                          (uint32_t*)hi, (uint32_t*)lo, n4);
}

extern "C" void kernel_launch(void* const* d_in, const int* in_sizes, int n_in,
                              void* d_out, int out_size)
{
    const float* x     = (const float*)d_in[0];
    const float* qkv_w = (const float*)d_in[1];
    const float* qkv_b = (const float*)d_in[2];
    const float* out_w = (const float*)d_in[3];
    const float* out_b = (const float*)d_in[4];
    const float* w1    = (const float*)d_in[5];
    const float* b1    = (const float*)d_in[6];
    const float* w2    = (const float*)d_in[7];
    const float* b2    = (const float*)d_in[8];
    const float* ln1w  = (const float*)d_in[9];
    const float* ln1b  = (const float*)d_in[10];
    const float* ln2w  = (const float*)d_in[11];
    const float* ln2b  = (const float*)d_in[12];

    float* outp = (float*)d_out;
    float* kdst = outp + (size_t)MTOK * DD;
    float* vdst = outp + (size_t)2 * MTOK * DD;

    float *qkv, *h1pre, *h1, *h2pre;
    bf16 *qkvh, *qkvl, *xh, *xl, *ah, *al, *h1h, *h1l, *midh, *midl;
    bf16 *wqh, *wql, *owh, *owl, *w1h, *w1l, *w2h, *w2l;
    cudaGetSymbolAddress((void**)&qkv,   g_qkv);
    cudaGetSymbolAddress((void**)&qkvh,  g_qkvh); cudaGetSymbolAddress((void**)&qkvl, g_qkvl);
    cudaGetSymbolAddress((void**)&h1pre, g_h1pre);
    cudaGetSymbolAddress((void**)&h1,    g_h1);
    cudaGetSymbolAddress((void**)&h2pre, g_h2pre);
    cudaGetSymbolAddress((void**)&xh,    g_xh);   cudaGetSymbolAddress((void**)&xl, g_xl);
    cudaGetSymbolAddress((void**)&ah,    g_ah);   cudaGetSymbolAddress((void**)&al, g_al);
    cudaGetSymbolAddress((void**)&h1h,   g_h1h);  cudaGetSymbolAddress((void**)&h1l, g_h1l);
    cudaGetSymbolAddress((void**)&midh,  g_midh); cudaGetSymbolAddress((void**)&midl, g_midl);
    cudaGetSymbolAddress((void**)&wqh,   g_wqh);  cudaGetSymbolAddress((void**)&wql, g_wql);
    cudaGetSymbolAddress((void**)&owh,   g_owh);  cudaGetSymbolAddress((void**)&owl, g_owl);
    cudaGetSymbolAddress((void**)&w1h,   g_w1h);  cudaGetSymbolAddress((void**)&w1l, g_w1l);
    cudaGetSymbolAddress((void**)&w2h,   g_w2h);  cudaGetSymbolAddress((void**)&w2l, g_w2l);

    cudaFuncSetAttribute(gemm_mma,
                         cudaFuncAttributeMaxDynamicSharedMemorySize, GEMM_SMEM);
    cudaFuncSetAttribute(flash_mma_k,
                         cudaFuncAttributeMaxDynamicSharedMemorySize, FA_SMEM);

    // 0) split weights + x into bf16 hi/lo
    cvt(qkv_w, wqh, wql, (size_t)3 * DD * DD);
    cvt(out_w, owh, owl, (size_t)DD * DD);
    cvt(w1,    w1h, w1l, (size_t)FF_DIM * DD);
    cvt(w2,    w2h, w2l, (size_t)DD * FF_DIM);
    cvt(x,     xh,  xl,  (size_t)MTOK * DD);

    // 1) QKV projection -> qkv fp32 + hi/lo bf16 [4096,3072]
    gemm_mma<<<dim3(3072 / 128, MTOK / 128), 256, GEMM_SMEM>>>(
        xh, xl, wqh, wql, qkv_b, nullptr, qkv, qkvh, qkvl,
        MTOK, 3 * DD, DD, 0);
    // 2) k/v caches (fp32 exact)
    copy_kv_k<<<(MTOK * (DD / 4)) / 256, 256>>>(qkv, kdst, vdst);
    // 3) tensor-core flash attention -> attn hi/lo bf16
    flash_mma_k<<<dim3(SS / 128, BB * HH), 256, FA_SMEM>>>(qkvh, qkvl, ah, al);
    // 4) out projection + residual x -> h1pre
    gemm_mma<<<dim3(DD / 128, MTOK / 128), 256, GEMM_SMEM>>>(
        ah, al, owh, owl, out_b, x, h1pre, nullptr, nullptr,
        MTOK, DD, DD, 0);
    // 5) LN1 -> h1 fp32 + hi/lo
    layernorm_k<<<MTOK, 256>>>(h1pre, ln1w, ln1b, h1, h1h, h1l);
    // 6) MLP up + ReLU -> mid hi/lo only
    gemm_mma<<<dim3(FF_DIM / 128, MTOK / 128), 256, GEMM_SMEM>>>(
        h1h, h1l, w1h, w1l, b1, nullptr, nullptr, midh, midl,
        MTOK, FF_DIM, DD, 1);
    // 7) MLP down + residual h1 -> h2pre
    gemm_mma<<<dim3(DD / 128, MTOK / 128), 256, GEMM_SMEM>>>(
        midh, midl, w2h, w2l, b2, h1, h2pre, nullptr, nullptr,
        MTOK, DD, FF_DIM, 0);
    // 8) LN2 -> out
    layernorm_k<<<MTOK, 256>>>(h2pre, ln2w, ln2b, outp, nullptr, nullptr);
}

// round 5
// speedup vs baseline: 3.2664x; 1.1272x over previous
#include <cuda_runtime.h>
#include <cuda_bf16.h>
#include <cstdint>

// Problem constants: B=2, S=2048, D=1024, H=16, hd=64, FF=4096
#define BB 2
#define SS 2048
#define DD 1024
#define HH 16
#define HD 64
#define FF_DIM 4096
#define MTOK (BB*SS)          // 4096 rows

typedef __nv_bfloat16 bf16;

// ---------------------------------------------------------------------------
// Scratch (device globals; no allocation allowed)
// ---------------------------------------------------------------------------
__device__ bf16 g_qkvh[(size_t)MTOK * 3 * DD], g_qkvl[(size_t)MTOK * 3 * DD];
__device__ float g_h1pre[(size_t)MTOK * DD];
__device__ float g_h1[(size_t)MTOK * DD];
__device__ float g_h2pre[(size_t)MTOK * DD];

__device__ bf16 g_xh[(size_t)MTOK * DD],      g_xl[(size_t)MTOK * DD];
__device__ bf16 g_ah[(size_t)MTOK * DD],      g_al[(size_t)MTOK * DD];   // attn out
__device__ bf16 g_h1h[(size_t)MTOK * DD],     g_h1l[(size_t)MTOK * DD];
__device__ bf16 g_midh[(size_t)MTOK * FF_DIM], g_midl[(size_t)MTOK * FF_DIM];
__device__ bf16 g_wqh[(size_t)3 * DD * DD],   g_wql[(size_t)3 * DD * DD];
__device__ bf16 g_owh[(size_t)DD * DD],       g_owl[(size_t)DD * DD];
__device__ bf16 g_w1h[(size_t)FF_DIM * DD],   g_w1l[(size_t)FF_DIM * DD];
__device__ bf16 g_w2h[(size_t)DD * FF_DIM],   g_w2l[(size_t)DD * FF_DIM];

// ---------------------------------------------------------------------------
// MMA / ldmatrix / cp.async helpers
// ---------------------------------------------------------------------------
__device__ __forceinline__ uint32_t smem_u32(const void* p) {
    uint32_t a;
    asm("{ .reg .u64 t; cvta.to.shared.u64 t, %1; cvt.u32.u64 %0, t; }"
        : "=r"(a) : "l"(p));
    return a;
}
__device__ __forceinline__ void ldsm4(uint32_t* r, uint32_t a) {
    asm volatile("ldmatrix.sync.aligned.m8n8.x4.shared.b16 {%0,%1,%2,%3}, [%4];"
                 : "=r"(r[0]), "=r"(r[1]), "=r"(r[2]), "=r"(r[3]) : "r"(a));
}
__device__ __forceinline__ void ldsm4t(uint32_t* r, uint32_t a) {
    asm volatile("ldmatrix.sync.aligned.m8n8.x4.trans.shared.b16 {%0,%1,%2,%3}, [%4];"
                 : "=r"(r[0]), "=r"(r[1]), "=r"(r[2]), "=r"(r[3]) : "r"(a));
}
__device__ __forceinline__ void mma16816(float* c, const uint32_t* a, const uint32_t* b) {
    asm volatile(
        "mma.sync.aligned.m16n8k16.row.col.f32.bf16.bf16.f32 "
        "{%0,%1,%2,%3}, {%4,%5,%6,%7}, {%8,%9}, {%0,%1,%2,%3};"
        : "+f"(c[0]), "+f"(c[1]), "+f"(c[2]), "+f"(c[3])
        : "r"(a[0]), "r"(a[1]), "r"(a[2]), "r"(a[3]), "r"(b[0]), "r"(b[1]));
}
#define CP16(dst, src) \
    asm volatile("cp.async.cg.shared.global [%0], [%1], 16;" :: "r"(dst), "l"(src) : "memory")
#define CP_COMMIT() asm volatile("cp.async.commit_group;" ::: "memory")
#define CP_WAIT1()  asm volatile("cp.async.wait_group 1;" ::: "memory")
#define CP_WAIT0()  asm volatile("cp.async.wait_group 0;" ::: "memory")

// 128B-row tile (flash): row stride 128B, chunk ch swizzled by row&7.
__device__ __forceinline__ uint32_t tile_addr(uint32_t base, int row, int ch) {
    return base + (uint32_t)row * 128u + (uint32_t)((ch ^ (row & 7)) << 4);
}
// paired-row tile (gemm): [128][32] bf16 in 64 smem rows of 128B.
// matrix row r, 16B k-chunk k (0..3): s=r>>1, c=((r&1)<<2)|k, swz c^(s&7).
__device__ __forceinline__ uint32_t tile2_addr(uint32_t base, int r, int k) {
    const int s = r >> 1;
    const int c = ((r & 1) << 2) | k;
    return base + (uint32_t)s * 128u + (uint32_t)((c ^ (s & 7)) << 4);
}
__device__ __forceinline__ uint32_t pack_hi(float a, float b) {
    __nv_bfloat162 h = __halves2bfloat162(__float2bfloat16(a), __float2bfloat16(b));
    return *(uint32_t*)&h;
}
__device__ __forceinline__ uint32_t pack_lo(float a, float b) {
    bf16 ha = __float2bfloat16(a), hb = __float2bfloat16(b);
    __nv_bfloat162 l = __halves2bfloat162(__float2bfloat16(a - __bfloat162float(ha)),
                                          __float2bfloat16(b - __bfloat162float(hb)));
    return *(uint32_t*)&l;
}

// ---------------------------------------------------------------------------
// Split-bf16 tensor-core GEMM: C[M,N] = (Ah+Al)@(Wh+Wl)^T + bias (+res)(+relu)
// 128x128 CTA tile, 8 warps (2Mx4N), warp tile 64x32, K-stage 32, 2 stages.
// Smem 64KB -> 2 CTAs/SM. Optional fused kv-cache split output (QKV mode).
// ---------------------------------------------------------------------------
#define GEMM_SMEM (2 * 4 * 8192)   // 64KB

__global__ __launch_bounds__(256, 2) void gemm_mma(
    const bf16* __restrict__ Ah, const bf16* __restrict__ Al,
    const bf16* __restrict__ Wh, const bf16* __restrict__ Wl,
    const float* __restrict__ bias, const float* __restrict__ res,
    float* __restrict__ C, bf16* __restrict__ Chi, bf16* __restrict__ Clo,
    float* __restrict__ kd, float* __restrict__ vd,
    int M, int N, int K, int relu)
{
    extern __shared__ char dsm[];
    const uint32_t sb = smem_u32(dsm);

    const int tid = threadIdx.x;
    const int lid = tid & 31;
    const int wid = tid >> 5;
    const int wm = wid & 1;
    const int wn = wid >> 1;
    const int bm = blockIdx.y * 128, bn = blockIdx.x * 128;

    const bf16* gs[4] = { Ah + (size_t)bm * K, Al + (size_t)bm * K,
                          Wh + (size_t)bn * K, Wl + (size_t)bn * K };

    float acc[4][4][4];
#pragma unroll
    for (int i = 0; i < 4; ++i)
#pragma unroll
        for (int j = 0; j < 4; ++j)
#pragma unroll
            for (int k = 0; k < 4; ++k) acc[i][j][k] = 0.f;

    const int NC = K >> 5;

    auto load_stage = [&](int stage, int kk) {
        const uint32_t stb = sb + (uint32_t)stage * 32768u;
        const int r  = tid >> 1;
        const int k0 = (tid & 1) * 2;
#pragma unroll
        for (int t4 = 0; t4 < 4; ++t4) {
            const uint32_t tb = stb + (uint32_t)t4 * 8192u;
            const bf16* g = gs[t4] + kk + (size_t)r * K;
#pragma unroll
            for (int j = 0; j < 2; ++j)
                CP16(tile2_addr(tb, r, k0 + j), (const char*)(g + (k0 + j) * 8));
        }
        CP_COMMIT();
    };

    load_stage(0, 0);

    const int arow = lid & 15;
    const int achd = lid >> 4;

    for (int c = 0; c < NC; ++c) {
        if (c + 1 < NC) { load_stage((c + 1) & 1, (c + 1) << 5); CP_WAIT1(); }
        else            { CP_WAIT0(); }
        __syncthreads();

        const uint32_t stb = sb + (uint32_t)(c & 1) * 32768u;

#pragma unroll
        for (int ks = 0; ks < 2; ++ks) {
            const int chk = ks * 2 + achd;
            uint32_t ah[4][4], al[4][4];
#pragma unroll
            for (int mt = 0; mt < 4; ++mt) {
                const int r = wm * 64 + mt * 16 + arow;
                ldsm4(ah[mt], tile2_addr(stb, r, chk));
                ldsm4(al[mt], tile2_addr(stb + 8192u, r, chk));
            }
            uint32_t bh[4][2], bl[4][2];
#pragma unroll
            for (int ntp = 0; ntp < 2; ++ntp) {
                const int r = wn * 32 + ntp * 16 + arow;
                uint32_t t[4], u[4];
                ldsm4(t, tile2_addr(stb + 16384u, r, chk));
                ldsm4(u, tile2_addr(stb + 24576u, r, chk));
                bh[2 * ntp][0] = t[0]; bh[2 * ntp][1] = t[2];
                bh[2 * ntp + 1][0] = t[1]; bh[2 * ntp + 1][1] = t[3];
                bl[2 * ntp][0] = u[0]; bl[2 * ntp][1] = u[2];
                bl[2 * ntp + 1][0] = u[1]; bl[2 * ntp + 1][1] = u[3];
            }
            // term-major ordering: 16 independent MMAs per term
#pragma unroll
            for (int mt = 0; mt < 4; ++mt)
#pragma unroll
                for (int nt = 0; nt < 4; ++nt)
                    mma16816(acc[mt][nt], ah[mt], bh[nt]);
#pragma unroll
            for (int mt = 0; mt < 4; ++mt)
#pragma unroll
                for (int nt = 0; nt < 4; ++nt)
                    mma16816(acc[mt][nt], ah[mt], bl[nt]);
#pragma unroll
            for (int mt = 0; mt < 4; ++mt)
#pragma unroll
                for (int nt = 0; nt < 4; ++nt)
                    mma16816(acc[mt][nt], al[mt], bh[nt]);
        }
        __syncthreads();
    }

    const int l4 = lid >> 2;
    const int l2 = (lid & 3) * 2;
#pragma unroll
    for (int mt = 0; mt < 4; ++mt) {
#pragma unroll
        for (int nt = 0; nt < 4; ++nt) {
            const int col = bn + wn * 32 + nt * 8 + l2;
#pragma unroll
            for (int half = 0; half < 2; ++half) {
                const int row = bm + wm * 64 + mt * 16 + l4 + half * 8;
                float v0 = acc[mt][nt][2 * half + 0];
                float v1 = acc[mt][nt][2 * half + 1];
                v0 += bias[col]; v1 += bias[col + 1];
                const size_t o = (size_t)row * N + col;
                if (res) { v0 += res[o]; v1 += res[o + 1]; }
                if (relu) { v0 = fmaxf(v0, 0.f); v1 = fmaxf(v1, 0.f); }
                if (C) *(float2*)(C + o) = make_float2(v0, v1);
                if (kd) {   // QKV mode: write fp32 k/v cache slices directly
                    if (col >= 2048)
                        *(float2*)(vd + (size_t)row * DD + col - 2048) = make_float2(v0, v1);
                    else if (col >= 1024)
                        *(float2*)(kd + (size_t)row * DD + col - 1024) = make_float2(v0, v1);
                }
                if (Chi) {
                    *(uint32_t*)(Chi + o) = pack_hi(v0, v1);
                    *(uint32_t*)(Clo + o) = pack_lo(v0, v1);
                }
            }
        }
    }
}

// ---------------------------------------------------------------------------
// fp32 -> (hi, lo) bf16 split
// ---------------------------------------------------------------------------
__global__ __launch_bounds__(256) void cvt_hilo_k(
    const float4* __restrict__ in, uint32_t* __restrict__ hi,
    uint32_t* __restrict__ lo, int n4)
{
    int i = blockIdx.x * blockDim.x + threadIdx.x;
    if (i >= n4) return;
    float4 v = in[i];
    hi[2 * i]     = pack_hi(v.x, v.y);
    hi[2 * i + 1] = pack_hi(v.z, v.w);
    lo[2 * i]     = pack_lo(v.x, v.y);
    lo[2 * i + 1] = pack_lo(v.z, v.w);
}

// ---------------------------------------------------------------------------
// Tensor-core flash attention, causal, split-bf16 (3-term), online softmax.
// CTA = 128 queries of one (b,h); 8 warps x 16 query rows; K-blocks of 64.
// ---------------------------------------------------------------------------
#define FA_SMEM (32768 + 2 * 32768)

__global__ __launch_bounds__(256) void flash_mma_k(
    const bf16* __restrict__ qh, const bf16* __restrict__ ql,
    bf16* __restrict__ oh, bf16* __restrict__ ol)
{
    extern __shared__ char dsm[];
    const uint32_t sb = smem_u32(dsm);
    const uint32_t Qh = sb, Ql = sb + 16384u;

    const int tid = threadIdx.x;
    const int lid = tid & 31;
    const int w   = tid >> 5;
    const int q0  = blockIdx.x * 128;
    const int b   = blockIdx.y >> 4;
    const int h   = blockIdx.y & 15;
    const size_t grow = (size_t)(b * SS);

    auto load_q = [&]() {
        const int row = tid >> 1;
        const int cb  = (tid & 1) * 4;
        const size_t src = (grow + q0 + row) * 3072 + h * HD;
#pragma unroll
        for (int j = 0; j < 4; ++j) {
            const int ch = cb + j;
            CP16(tile_addr(Qh, row, ch), (const char*)(qh + src + ch * 8));
            CP16(tile_addr(Ql, row, ch), (const char*)(ql + src + ch * 8));
        }
    };
    auto load_kv = [&](int buf, int k0) {
        const uint32_t bbase = sb + 32768u + (uint32_t)buf * 32768u;
        const int row = tid >> 2;
        const int cb  = (tid & 3) * 2;
        const size_t srcK = (grow + k0 + row) * 3072 + 1024 + h * HD;
        const size_t srcV = srcK + 1024;
#pragma unroll
        for (int j = 0; j < 2; ++j) {
            const int ch = cb + j;
            const uint32_t off = tile_addr(0, row, ch);
            CP16(bbase + off,           (const char*)(qh + srcK + ch * 8));
            CP16(bbase + 8192u + off,   (const char*)(ql + srcK + ch * 8));
            CP16(bbase + 16384u + off,  (const char*)(qh + srcV + ch * 8));
            CP16(bbase + 24576u + off,  (const char*)(ql + srcV + ch * 8));
        }
    };

    load_q();
    load_kv(0, 0);
    CP_COMMIT();

    const int nblk = q0 / 64 + 2;
    const int arow = lid & 15;
    const int achd = lid >> 4;

    uint32_t qfh[4][4], qfl[4][4];
    float of[8][4];
#pragma unroll
    for (int i = 0; i < 8; ++i)
#pragma unroll
        for (int j = 0; j < 4; ++j) of[i][j] = 0.f;
    float m0 = -1e30f, m1 = -1e30f, l0 = 0.f, l1 = 0.f;

    const int row_lo = lid >> 2;

    for (int c = 0; c < nblk; ++c) {
        if (c + 1 < nblk) { load_kv((c + 1) & 1, (c + 1) * 64); CP_COMMIT(); CP_WAIT1(); }
        else              { CP_WAIT0(); }
        __syncthreads();

        if (c == 0) {
#pragma unroll
            for (int ks = 0; ks < 4; ++ks) {
                const uint32_t ad = tile_addr(Qh, w * 16 + arow, ks * 2 + achd);
                ldsm4(qfh[ks], ad);
                ldsm4(qfl[ks], ad + 16384u);
            }
        }

        const uint32_t kb = sb + 32768u + (uint32_t)(c & 1) * 32768u;
        const int k0 = c * 64;

        float sf[8][4];
#pragma unroll
        for (int i = 0; i < 8; ++i)
#pragma unroll
            for (int j = 0; j < 4; ++j) sf[i][j] = 0.f;

#pragma unroll
        for (int ks = 0; ks < 4; ++ks) {
            uint32_t bh[8][2], bl[8][2];
#pragma unroll
            for (int ntp = 0; ntp < 4; ++ntp) {
                const uint32_t bd = tile_addr(kb, ntp * 16 + arow, ks * 2 + achd);
                uint32_t t[4], u[4];
                ldsm4(t, bd);
                ldsm4(u, bd + 8192u);
                bh[2 * ntp][0] = t[0]; bh[2 * ntp][1] = t[2];
                bh[2 * ntp + 1][0] = t[1]; bh[2 * ntp + 1][1] = t[3];
                bl[2 * ntp][0] = u[0]; bl[2 * ntp][1] = u[2];
                bl[2 * ntp + 1][0] = u[1]; bl[2 * ntp + 1][1] = u[3];
            }
#pragma unroll
            for (int nt = 0; nt < 8; ++nt) mma16816(sf[nt], qfh[ks], bh[nt]);
#pragma unroll
            for (int nt = 0; nt < 8; ++nt) mma16816(sf[nt], qfh[ks], bl[nt]);
#pragma unroll
            for (int nt = 0; nt < 8; ++nt) mma16816(sf[nt], qfl[ks], bh[nt]);
        }

        const int grow0 = q0 + w * 16 + row_lo;
        const int grow1 = grow0 + 8;
        const bool need_mask = (k0 + 63 > q0 + w * 16);
#pragma unroll
        for (int nt = 0; nt < 8; ++nt) {
            const int col = k0 + nt * 8 + 2 * (lid & 3);
#pragma unroll
            for (int j = 0; j < 4; ++j) sf[nt][j] *= 0.125f;
            if (need_mask) {
                if (col     > grow0) sf[nt][0] = -1e30f;
                if (col + 1 > grow0) sf[nt][1] = -1e30f;
                if (col     > grow1) sf[nt][2] = -1e30f;
                if (col + 1 > grow1) sf[nt][3] = -1e30f;
            }
        }

        float tm0 = -1e30f, tm1 = -1e30f;
#pragma unroll
        for (int nt = 0; nt < 8; ++nt) {
            tm0 = fmaxf(tm0, fmaxf(sf[nt][0], sf[nt][1]));
            tm1 = fmaxf(tm1, fmaxf(sf[nt][2], sf[nt][3]));
        }
        tm0 = fmaxf(tm0, __shfl_xor_sync(0xffffffffu, tm0, 1));
        tm0 = fmaxf(tm0, __shfl_xor_sync(0xffffffffu, tm0, 2));
        tm1 = fmaxf(tm1, __shfl_xor_sync(0xffffffffu, tm1, 1));
        tm1 = fmaxf(tm1, __shfl_xor_sync(0xffffffffu, tm1, 2));

        const float mn0 = fmaxf(m0, tm0), mn1 = fmaxf(m1, tm1);
        const float cr0 = __expf(m0 - mn0), cr1 = __expf(m1 - mn1);
        m0 = mn0; m1 = mn1;

        float ps0 = 0.f, ps1 = 0.f;
#pragma unroll
        for (int nt = 0; nt < 8; ++nt) {
            sf[nt][0] = __expf(sf[nt][0] - mn0);
            sf[nt][1] = __expf(sf[nt][1] - mn0);
            sf[nt][2] = __expf(sf[nt][2] - mn1);
            sf[nt][3] = __expf(sf[nt][3] - mn1);
            ps0 += sf[nt][0] + sf[nt][1];
            ps1 += sf[nt][2] + sf[nt][3];
        }
        ps0 += __shfl_xor_sync(0xffffffffu, ps0, 1);
        ps0 += __shfl_xor_sync(0xffffffffu, ps0, 2);
        ps1 += __shfl_xor_sync(0xffffffffu, ps1, 1);
        ps1 += __shfl_xor_sync(0xffffffffu, ps1, 2);
        l0 = l0 * cr0 + ps0;
        l1 = l1 * cr1 + ps1;
#pragma unroll
        for (int nt = 0; nt < 8; ++nt) {
            of[nt][0] *= cr0; of[nt][1] *= cr0;
            of[nt][2] *= cr1; of[nt][3] *= cr1;
        }

        uint32_t pah[4][4], pal[4][4];
#pragma unroll
        for (int kk = 0; kk < 4; ++kk) {
            pah[kk][0] = pack_hi(sf[2 * kk][0], sf[2 * kk][1]);
            pah[kk][1] = pack_hi(sf[2 * kk][2], sf[2 * kk][3]);
            pah[kk][2] = pack_hi(sf[2 * kk + 1][0], sf[2 * kk + 1][1]);
            pah[kk][3] = pack_hi(sf[2 * kk + 1][2], sf[2 * kk + 1][3]);
            pal[kk][0] = pack_lo(sf[2 * kk][0], sf[2 * kk][1]);
            pal[kk][1] = pack_lo(sf[2 * kk][2], sf[2 * kk][3]);
            pal[kk][2] = pack_lo(sf[2 * kk + 1][0], sf[2 * kk + 1][1]);
            pal[kk][3] = pack_lo(sf[2 * kk + 1][2], sf[2 * kk + 1][3]);
        }

        const uint32_t vb = kb + 16384u;
#pragma unroll
        for (int ks = 0; ks < 4; ++ks) {
            uint32_t vh[8][2], vl[8][2];
#pragma unroll
            for (int ntp = 0; ntp < 4; ++ntp) {
                const int krow = ks * 16 + arow;
                const uint32_t vd2 = tile_addr(vb, krow, ntp * 2 + achd);
                uint32_t t[4], u[4];
                ldsm4t(t, vd2);
                ldsm4t(u, vd2 + 8192u);
                vh[2 * ntp][0] = t[0]; vh[2 * ntp][1] = t[1];
                vh[2 * ntp + 1][0] = t[2]; vh[2 * ntp + 1][1] = t[3];
                vl[2 * ntp][0] = u[0]; vl[2 * ntp][1] = u[1];
                vl[2 * ntp + 1][0] = u[2]; vl[2 * ntp + 1][1] = u[3];
            }
#pragma unroll
            for (int nt = 0; nt < 8; ++nt) mma16816(of[nt], pah[ks], vh[nt]);
#pragma unroll
            for (int nt = 0; nt < 8; ++nt) mma16816(of[nt], pah[ks], vl[nt]);
#pragma unroll
            for (int nt = 0; nt < 8; ++nt) mma16816(of[nt], pal[ks], vh[nt]);
        }
        __syncthreads();
    }

    const float iv0 = 1.0f / l0, iv1 = 1.0f / l1;
    const size_t r0 = (grow + q0 + w * 16 + row_lo) * DD + h * HD;
    const size_t r1 = r0 + 8 * DD;
#pragma unroll
    for (int nt = 0; nt < 8; ++nt) {
        const int cofs = nt * 8 + 2 * (lid & 3);
        float v0 = of[nt][0] * iv0, v1 = of[nt][1] * iv0;
        float v2 = of[nt][2] * iv1, v3 = of[nt][3] * iv1;
        *(uint32_t*)(oh + r0 + cofs) = pack_hi(v0, v1);
        *(uint32_t*)(ol + r0 + cofs) = pack_lo(v0, v1);
        *(uint32_t*)(oh + r1 + cofs) = pack_hi(v2, v3);
        *(uint32_t*)(ol + r1 + cofs) = pack_lo(v2, v3);
    }
}

// ---------------------------------------------------------------------------
// LayerNorm over D=1024, optional fused bf16 hi/lo output
// ---------------------------------------------------------------------------
__global__ __launch_bounds__(256) void layernorm_k(
    const float* __restrict__ in, const float* __restrict__ w,
    const float* __restrict__ b, float* __restrict__ out,
    bf16* __restrict__ ohi, bf16* __restrict__ olo)
{
    __shared__ float red[8];
    __shared__ float bval;
    const int tid = threadIdx.x;
    const size_t base = (size_t)blockIdx.x * DD;

    float4 v = ((const float4*)(in + base))[tid];
    float s = v.x + v.y + v.z + v.w;
#pragma unroll
    for (int off = 16; off; off >>= 1) s += __shfl_xor_sync(0xffffffffu, s, off);
    if ((tid & 31) == 0) red[tid >> 5] = s;
    __syncthreads();
    if (tid == 0) {
        float t = 0.f;
#pragma unroll
        for (int i = 0; i < 8; ++i) t += red[i];
        bval = t * (1.0f / DD);
    }
    __syncthreads();
    const float mu = bval;
    __syncthreads();

    float dx = v.x - mu, dy = v.y - mu, dz = v.z - mu, dw = v.w - mu;
    float q = dx * dx + dy * dy + dz * dz + dw * dw;
#pragma unroll
    for (int off = 16; off; off >>= 1) q += __shfl_xor_sync(0xffffffffu, q, off);
    if ((tid & 31) == 0) red[tid >> 5] = q;
    __syncthreads();
    if (tid == 0) {
        float t = 0.f;
#pragma unroll
        for (int i = 0; i < 8; ++i) t += red[i];
        bval = t * (1.0f / DD);
    }
    __syncthreads();
    const float inv = rsqrtf(bval + 1e-5f);

    float4 w4 = ((const float4*)w)[tid];
    float4 b4 = ((const float4*)b)[tid];
    float4 r = make_float4(dx * inv * w4.x + b4.x,
                           dy * inv * w4.y + b4.y,
                           dz * inv * w4.z + b4.z,
                           dw * inv * w4.w + b4.w);
    ((float4*)(out + base))[tid] = r;
    if (ohi) {
        *(uint32_t*)(ohi + base + 4 * tid)     = pack_hi(r.x, r.y);
        *(uint32_t*)(ohi + base + 4 * tid + 2) = pack_hi(r.z, r.w);
        *(uint32_t*)(olo + base + 4 * tid)     = pack_lo(r.x, r.y);
        *(uint32_t*)(olo + base + 4 * tid + 2) = pack_lo(r.z, r.w);
    }
}

// ---------------------------------------------------------------------------
// Launch
// ---------------------------------------------------------------------------
static inline void cvt(const float* in, bf16* hi, bf16* lo, size_t n) {
    int n4 = (int)(n / 4);
    cvt_hilo_k<<<(n4 + 255) / 256, 256>>>((const float4*)in,
                                          (uint32_t*)hi, (uint32_t*)lo, n4);
}

extern "C" void kernel_launch(void* const* d_in, const int* in_sizes, int n_in,
                              void* d_out, int out_size)
{
    const float* x     = (const float*)d_in[0];
    const float* qkv_w = (const float*)d_in[1];
    const float* qkv_b = (const float*)d_in[2];
    const float* out_w = (const float*)d_in[3];
    const float* out_b = (const float*)d_in[4];
    const float* w1    = (const float*)d_in[5];
    const float* b1    = (const float*)d_in[6];
    const float* w2    = (const float*)d_in[7];
    const float* b2    = (const float*)d_in[8];
    const float* ln1w  = (const float*)d_in[9];
    const float* ln1b  = (const float*)d_in[10];
    const float* ln2w  = (const float*)d_in[11];
    const float* ln2b  = (const float*)d_in[12];

    float* outp = (float*)d_out;
    float* kdst = outp + (size_t)MTOK * DD;
    float* vdst = outp + (size_t)2 * MTOK * DD;

    float *h1pre, *h1, *h2pre;
    bf16 *qkvh, *qkvl, *xh, *xl, *ah, *al, *h1h, *h1l, *midh, *midl;
    bf16 *wqh, *wql, *owh, *owl, *w1h, *w1l, *w2h, *w2l;
    cudaGetSymbolAddress((void**)&qkvh,  g_qkvh); cudaGetSymbolAddress((void**)&qkvl, g_qkvl);
    cudaGetSymbolAddress((void**)&h1pre, g_h1pre);
    cudaGetSymbolAddress((void**)&h1,    g_h1);
    cudaGetSymbolAddress((void**)&h2pre, g_h2pre);
    cudaGetSymbolAddress((void**)&xh,    g_xh);   cudaGetSymbolAddress((void**)&xl, g_xl);
    cudaGetSymbolAddress((void**)&ah,    g_ah);   cudaGetSymbolAddress((void**)&al, g_al);
    cudaGetSymbolAddress((void**)&h1h,   g_h1h);  cudaGetSymbolAddress((void**)&h1l, g_h1l);
    cudaGetSymbolAddress((void**)&midh,  g_midh); cudaGetSymbolAddress((void**)&midl, g_midl);
    cudaGetSymbolAddress((void**)&wqh,   g_wqh);  cudaGetSymbolAddress((void**)&wql, g_wql);
    cudaGetSymbolAddress((void**)&owh,   g_owh);  cudaGetSymbolAddress((void**)&owl, g_owl);
    cudaGetSymbolAddress((void**)&w1h,   g_w1h);  cudaGetSymbolAddress((void**)&w1l, g_w1l);
    cudaGetSymbolAddress((void**)&w2h,   g_w2h);  cudaGetSymbolAddress((void**)&w2l, g_w2l);

    cudaFuncSetAttribute(gemm_mma,
                         cudaFuncAttributeMaxDynamicSharedMemorySize, GEMM_SMEM);
    cudaFuncSetAttribute(flash_mma_k,
                         cudaFuncAttributeMaxDynamicSharedMemorySize, FA_SMEM);

    // 0) split weights + x into bf16 hi/lo
    cvt(qkv_w, wqh, wql, (size_t)3 * DD * DD);
    cvt(out_w, owh, owl, (size_t)DD * DD);
    cvt(w1,    w1h, w1l, (size_t)FF_DIM * DD);
    cvt(w2,    w2h, w2l, (size_t)DD * FF_DIM);
    cvt(x,     xh,  xl,  (size_t)MTOK * DD);

    // 1) QKV projection -> qkv hi/lo bf16; k/v fp32 slices straight to d_out
    gemm_mma<<<dim3(3072 / 128, MTOK / 128), 256, GEMM_SMEM>>>(
        xh, xl, wqh, wql, qkv_b, nullptr, nullptr, qkvh, qkvl, kdst, vdst,
        MTOK, 3 * DD, DD, 0);
    // 2) tensor-core flash attention -> attn hi/lo bf16
    flash_mma_k<<<dim3(SS / 128, BB * HH), 256, FA_SMEM>>>(qkvh, qkvl, ah, al);
    // 3) out projection + residual x -> h1pre
    gemm_mma<<<dim3(DD / 128, MTOK / 128), 256, GEMM_SMEM>>>(
        ah, al, owh, owl, out_b, x, h1pre, nullptr, nullptr, nullptr, nullptr,
        MTOK, DD, DD, 0);
    // 4) LN1 -> h1 fp32 + hi/lo
    layernorm_k<<<MTOK, 256>>>(h1pre, ln1w, ln1b, h1, h1h, h1l);
    // 5) MLP up + ReLU -> mid hi/lo only
    gemm_mma<<<dim3(FF_DIM / 128, MTOK / 128), 256, GEMM_SMEM>>>(
        h1h, h1l, w1h, w1l, b1, nullptr, nullptr, midh, midl, nullptr, nullptr,
        MTOK, FF_DIM, DD, 1);
    // 6) MLP down + residual h1 -> h2pre
    gemm_mma<<<dim3(DD / 128, MTOK / 128), 256, GEMM_SMEM>>>(
        midh, midl, w2h, w2l, b2, h1, h2pre, nullptr, nullptr, nullptr, nullptr,
        MTOK, DD, FF_DIM, 0);
    // 7) LN2 -> out
    layernorm_k<<<MTOK, 256>>>(h2pre, ln2w, ln2b, outp, nullptr, nullptr);
}